// round 14
// baseline (speedup 1.0000x reference)
#include <cuda_runtime.h>

#define Bc 2
#define Tc 2048
#define Cc 512
#define Hc 8
#define HDc 64
#define TOPKc 64
#define BHc (Bc*Hc)
#define Mr (Bc*Tc)

// Scratch (device globals; allocations forbidden)
__device__ float g_Qh[BHc*Tc*HDc];
__device__ float g_Kh[BHc*Tc*HDc];
__device__ float g_Vh[BHc*Tc*HDc];
__device__ float g_Y [Bc*Tc*Cc];
__device__ unsigned g_SU[(size_t)BHc*Tc*Tc];   // scores as ordered uints

// ---------------------------------------------------------------------------
// helpers
// ---------------------------------------------------------------------------
__device__ __forceinline__ unsigned f2u(float f) {
    unsigned b = __float_as_uint(f);
    return b ^ ((unsigned)((int)b >> 31) | 0x80000000u);
}
__device__ __forceinline__ float u2f(unsigned u) {
    unsigned b = (u & 0x80000000u) ? (u ^ 0x80000000u) : ~u;
    return __uint_as_float(b);
}

// pick bin containing rank `need` scanning 255..0; returns (byte<<16)|rem_need
__device__ __forceinline__ int radix_pick(const int* hist, int need, int lane) {
    int s = 0;
    #pragma unroll
    for (int j = 0; j < 8; j++) s += hist[255 - lane * 8 - j];
    int cum = s;
    #pragma unroll
    for (int off = 1; off < 32; off <<= 1) {
        int v = __shfl_up_sync(0xffffffffu, cum, off);
        if (lane >= off) cum += v;
    }
    unsigned bal = __ballot_sync(0xffffffffu, cum >= need);
    int selL = __ffs(bal) - 1;
    int above = __shfl_sync(0xffffffffu, cum - s, selL);
    int sneed = need - above;
    int res = 0;
    if (lane == selL) {
        int c = 0;
        #pragma unroll 1
        for (int j = 0; j < 8; j++) {
            int b = 255 - selL * 8 - j;
            int h = hist[b];
            if (c + h >= sneed) { res = (b << 16) | (sneed - c); break; }
            c += h;
        }
    }
    return __shfl_sync(0xffffffffu, res, selL);
}

// ---------------------------------------------------------------------------
// Fused QKV GEMM (round-8 exact, measured 157us).
// ---------------------------------------------------------------------------
__global__ void __launch_bounds__(256, 2)
qkv_kernel(const float* __restrict__ A,
           const float* __restrict__ Wq, const float* __restrict__ bq,
           const float* __restrict__ Wk, const float* __restrict__ bk,
           const float* __restrict__ Wv, const float* __restrict__ bv,
           float* __restrict__ Qh, float* __restrict__ Kh, float* __restrict__ Vh)
{
    int z = blockIdx.z;
    const float* W    = (z == 0) ? Wq : (z == 1) ? Wk : Wv;
    const float* bias = (z == 0) ? bq : (z == 1) ? bk : bv;
    float* out        = (z == 0) ? Qh : (z == 1) ? Kh : Vh;

    __shared__ float As[2][8][128];
    __shared__ float Bs[2][8][128];

    int tid = threadIdx.x;
    int bm = blockIdx.y * 128;
    int bn = blockIdx.x * 128;
    int ty = tid >> 4;
    int tx = tid & 15;

    int arow = tid >> 1;
    int akq  = (tid & 1) * 4;
    int brow = tid >> 5;
    int bcol = (tid & 31) * 4;

    const float* Ag = A + (size_t)(bm + arow) * Cc + akq;
    const float* Wg = W + (size_t)brow * Cc + bn + bcol;

    float acc[8][8];
    #pragma unroll
    for (int i = 0; i < 8; i++)
        #pragma unroll
        for (int j = 0; j < 8; j++) acc[i][j] = 0.f;

    {
        float4 av = *reinterpret_cast<const float4*>(Ag);
        float4 bv4 = *reinterpret_cast<const float4*>(Wg);
        As[0][akq + 0][arow] = av.x;
        As[0][akq + 1][arow] = av.y;
        As[0][akq + 2][arow] = av.z;
        As[0][akq + 3][arow] = av.w;
        *reinterpret_cast<float4*>(&Bs[0][brow][bcol]) = bv4;
    }
    __syncthreads();

    #pragma unroll 1
    for (int kb = 0; kb < 64; kb++) {
        int cur = kb & 1;
        float4 an, bnv;
        if (kb < 63) {
            an  = *reinterpret_cast<const float4*>(Ag + (kb + 1) * 8);
            bnv = *reinterpret_cast<const float4*>(Wg + (size_t)(kb + 1) * 8 * Cc);
        }
        #pragma unroll
        for (int k = 0; k < 8; k++) {
            float4 a0 = *reinterpret_cast<const float4*>(&As[cur][k][ty * 4]);
            float4 a1 = *reinterpret_cast<const float4*>(&As[cur][k][64 + ty * 4]);
            float4 b0 = *reinterpret_cast<const float4*>(&Bs[cur][k][tx * 4]);
            float4 b1 = *reinterpret_cast<const float4*>(&Bs[cur][k][64 + tx * 4]);
            float a[8] = {a0.x, a0.y, a0.z, a0.w, a1.x, a1.y, a1.z, a1.w};
            float b[8] = {b0.x, b0.y, b0.z, b0.w, b1.x, b1.y, b1.z, b1.w};
            #pragma unroll
            for (int i = 0; i < 8; i++)
                #pragma unroll
                for (int j = 0; j < 8; j++)
                    acc[i][j] += a[i] * b[j];
        }
        if (kb < 63) {
            int nxt = cur ^ 1;
            As[nxt][akq + 0][arow] = an.x;
            As[nxt][akq + 1][arow] = an.y;
            As[nxt][akq + 2][arow] = an.z;
            As[nxt][akq + 3][arow] = an.w;
            *reinterpret_cast<float4*>(&Bs[nxt][brow][bcol]) = bnv;
            __syncthreads();
        }
    }

    float4 bia0 = *reinterpret_cast<const float4*>(bias + bn + tx * 4);
    float4 bia1 = *reinterpret_cast<const float4*>(bias + bn + 64 + tx * 4);
    #pragma unroll
    for (int i = 0; i < 8; i++) {
        int r = (i < 4) ? (ty * 4 + i) : (64 + ty * 4 + (i - 4));
        int mrow = bm + r;
        int b = mrow >> 11;
        int t = mrow & (Tc - 1);
        float4 o0 = make_float4(acc[i][0] + bia0.x, acc[i][1] + bia0.y,
                                acc[i][2] + bia0.z, acc[i][3] + bia0.w);
        float4 o1 = make_float4(acc[i][4] + bia1.x, acc[i][5] + bia1.y,
                                acc[i][6] + bia1.z, acc[i][7] + bia1.w);
        if (z == 2) {
            float ss0 = o0.x*o0.x + o0.y*o0.y + o0.z*o0.z + o0.w*o0.w;
            float ss1 = o1.x*o1.x + o1.y*o1.y + o1.z*o1.z + o1.w*o1.w;
            #pragma unroll
            for (int off = 8; off; off >>= 1) {
                ss0 += __shfl_xor_sync(0xffffffffu, ss0, off);
                ss1 += __shfl_xor_sync(0xffffffffu, ss1, off);
            }
            float sc0 = 1.0f / fmaxf(sqrtf(ss0), 1e-12f);
            float sc1 = 1.0f / fmaxf(sqrtf(ss1), 1e-12f);
            o0.x *= sc0; o0.y *= sc0; o0.z *= sc0; o0.w *= sc0;
            o1.x *= sc1; o1.y *= sc1; o1.z *= sc1; o1.w *= sc1;
        }
        int n0 = bn + tx * 4;       int h0 = n0 >> 6, d0 = n0 & 63;
        int n1 = bn + 64 + tx * 4;  int h1 = n1 >> 6, d1 = n1 & 63;
        *reinterpret_cast<float4*>(out + ((size_t)((b * Hc + h0) * Tc + t) << 6) + d0) = o0;
        *reinterpret_cast<float4*>(out + ((size_t)((b * Hc + h1) * Tc + t) << 6) + d1) = o1;
    }
}

// ---------------------------------------------------------------------------
// Output projection GEMM (row-major out), r13 exact (measured 63us).
// ---------------------------------------------------------------------------
__global__ void __launch_bounds__(256, 2)
sgemm_kernel(const float* __restrict__ A, const float* __restrict__ W,
             const float* __restrict__ bias, float* __restrict__ out)
{
    __shared__ float As[2][8][128];
    __shared__ float Bs[2][8][128];

    int tid = threadIdx.x;
    int bm = blockIdx.y * 128;
    int bn = blockIdx.x * 128;
    int ty = tid >> 4;
    int tx = tid & 15;

    int arow = tid >> 1;
    int akq  = (tid & 1) * 4;
    int brow = tid >> 5;
    int bcol = (tid & 31) * 4;

    const float* Ag = A + (size_t)(bm + arow) * Cc + akq;
    const float* Wg = W + (size_t)brow * Cc + bn + bcol;

    float acc[8][8];
    #pragma unroll
    for (int i = 0; i < 8; i++)
        #pragma unroll
        for (int j = 0; j < 8; j++) acc[i][j] = 0.f;

    {
        float4 av = *reinterpret_cast<const float4*>(Ag);
        float4 bv4 = *reinterpret_cast<const float4*>(Wg);
        As[0][akq + 0][arow] = av.x;
        As[0][akq + 1][arow] = av.y;
        As[0][akq + 2][arow] = av.z;
        As[0][akq + 3][arow] = av.w;
        *reinterpret_cast<float4*>(&Bs[0][brow][bcol]) = bv4;
    }
    __syncthreads();

    #pragma unroll 1
    for (int kb = 0; kb < 64; kb++) {
        int cur = kb & 1;
        float4 an, bnv;
        if (kb < 63) {
            an  = *reinterpret_cast<const float4*>(Ag + (kb + 1) * 8);
            bnv = *reinterpret_cast<const float4*>(Wg + (size_t)(kb + 1) * 8 * Cc);
        }
        #pragma unroll
        for (int k = 0; k < 8; k++) {
            float4 a0 = *reinterpret_cast<const float4*>(&As[cur][k][ty * 4]);
            float4 a1 = *reinterpret_cast<const float4*>(&As[cur][k][64 + ty * 4]);
            float4 b0 = *reinterpret_cast<const float4*>(&Bs[cur][k][tx * 4]);
            float4 b1 = *reinterpret_cast<const float4*>(&Bs[cur][k][64 + tx * 4]);
            float a[8] = {a0.x, a0.y, a0.z, a0.w, a1.x, a1.y, a1.z, a1.w};
            float b[8] = {b0.x, b0.y, b0.z, b0.w, b1.x, b1.y, b1.z, b1.w};
            #pragma unroll
            for (int i = 0; i < 8; i++)
                #pragma unroll
                for (int j = 0; j < 8; j++)
                    acc[i][j] += a[i] * b[j];
        }
        if (kb < 63) {
            int nxt = cur ^ 1;
            As[nxt][akq + 0][arow] = an.x;
            As[nxt][akq + 1][arow] = an.y;
            As[nxt][akq + 2][arow] = an.z;
            As[nxt][akq + 3][arow] = an.w;
            *reinterpret_cast<float4*>(&Bs[nxt][brow][bcol]) = bnv;
            __syncthreads();
        }
    }

    float4 bia0 = *reinterpret_cast<const float4*>(bias + bn + tx * 4);
    float4 bia1 = *reinterpret_cast<const float4*>(bias + bn + 64 + tx * 4);
    #pragma unroll
    for (int i = 0; i < 8; i++) {
        int r = (i < 4) ? (ty * 4 + i) : (64 + ty * 4 + (i - 4));
        int mrow = bm + r;
        float4 o0 = make_float4(acc[i][0] + bia0.x, acc[i][1] + bia0.y,
                                acc[i][2] + bia0.z, acc[i][3] + bia0.w);
        float4 o1 = make_float4(acc[i][4] + bia1.x, acc[i][5] + bia1.y,
                                acc[i][6] + bia1.z, acc[i][7] + bia1.w);
        *reinterpret_cast<float4*>(out + (size_t)mrow * Cc + bn + tx * 4) = o0;
        *reinterpret_cast<float4*>(out + (size_t)mrow * Cc + bn + 64 + tx * 4) = o1;
    }
}

// ---------------------------------------------------------------------------
// Score GEMM (r13 exact): su[q][k] = f2u((Q.K)*0.125), 128x128 tile/block.
// ---------------------------------------------------------------------------
__global__ void __launch_bounds__(256, 2)
score_kernel(const float* __restrict__ Qh, const float* __restrict__ Kh,
             unsigned* __restrict__ gsu)
{
    if (blockIdx.x > blockIdx.y) return;
    int bh = blockIdx.z;
    int q0 = blockIdx.y * 128;
    int k0 = blockIdx.x * 128;

    __shared__ float As[2][8][128];
    __shared__ float Bs[2][8][128];

    int tid = threadIdx.x;
    int ty = tid >> 4;
    int tx = tid & 15;

    int arow = tid >> 1;
    int akq  = (tid & 1) * 4;

    const float* Ag = Qh + ((size_t)(bh * Tc + q0) + arow) * HDc + akq;
    const float* Bg = Kh + ((size_t)(bh * Tc + k0) + arow) * HDc + akq;

    float acc[8][8];
    #pragma unroll
    for (int i = 0; i < 8; i++)
        #pragma unroll
        for (int j = 0; j < 8; j++) acc[i][j] = 0.f;

    {
        float4 av = *reinterpret_cast<const float4*>(Ag);
        float4 bv = *reinterpret_cast<const float4*>(Bg);
        As[0][akq + 0][arow] = av.x;
        As[0][akq + 1][arow] = av.y;
        As[0][akq + 2][arow] = av.z;
        As[0][akq + 3][arow] = av.w;
        Bs[0][akq + 0][arow] = bv.x;
        Bs[0][akq + 1][arow] = bv.y;
        Bs[0][akq + 2][arow] = bv.z;
        Bs[0][akq + 3][arow] = bv.w;
    }
    __syncthreads();

    #pragma unroll 1
    for (int kb = 0; kb < 8; kb++) {
        int cur = kb & 1;
        float4 an, bn;
        if (kb < 7) {
            an = *reinterpret_cast<const float4*>(Ag + (kb + 1) * 8);
            bn = *reinterpret_cast<const float4*>(Bg + (kb + 1) * 8);
        }
        #pragma unroll
        for (int k = 0; k < 8; k++) {
            float4 a0 = *reinterpret_cast<const float4*>(&As[cur][k][ty * 4]);
            float4 a1 = *reinterpret_cast<const float4*>(&As[cur][k][64 + ty * 4]);
            float4 b0 = *reinterpret_cast<const float4*>(&Bs[cur][k][tx * 4]);
            float4 b1 = *reinterpret_cast<const float4*>(&Bs[cur][k][64 + tx * 4]);
            float a[8] = {a0.x, a0.y, a0.z, a0.w, a1.x, a1.y, a1.z, a1.w};
            float b[8] = {b0.x, b0.y, b0.z, b0.w, b1.x, b1.y, b1.z, b1.w};
            #pragma unroll
            for (int i = 0; i < 8; i++)
                #pragma unroll
                for (int j = 0; j < 8; j++)
                    acc[i][j] += a[i] * b[j];
        }
        if (kb < 7) {
            int nxt = cur ^ 1;
            As[nxt][akq + 0][arow] = an.x;
            As[nxt][akq + 1][arow] = an.y;
            As[nxt][akq + 2][arow] = an.z;
            As[nxt][akq + 3][arow] = an.w;
            Bs[nxt][akq + 0][arow] = bn.x;
            Bs[nxt][akq + 1][arow] = bn.y;
            Bs[nxt][akq + 2][arow] = bn.z;
            Bs[nxt][akq + 3][arow] = bn.w;
            __syncthreads();
        }
    }

    #pragma unroll
    for (int i = 0; i < 8; i++) {
        int r = (i < 4) ? (ty * 4 + i) : (64 + ty * 4 + (i - 4));
        unsigned* dst = gsu + (size_t)(bh * Tc + q0 + r) * Tc + k0;
        uint4 u0, u1;
        u0.x = f2u(acc[i][0] * 0.125f); u0.y = f2u(acc[i][1] * 0.125f);
        u0.z = f2u(acc[i][2] * 0.125f); u0.w = f2u(acc[i][3] * 0.125f);
        u1.x = f2u(acc[i][4] * 0.125f); u1.y = f2u(acc[i][5] * 0.125f);
        u1.z = f2u(acc[i][6] * 0.125f); u1.w = f2u(acc[i][7] * 0.125f);
        *reinterpret_cast<uint4*>(dst + tx * 4)      = u0;
        *reinterpret_cast<uint4*>(dst + 64 + tx * 4) = u1;
    }
}

// ---------------------------------------------------------------------------
// Select kernel v2: 2 DRAM sweeps instead of 5.
// Sweep 1 (uint4): top-byte hist + row max. Sweep 2 (uint4): compact definite
// keeps (top byte > b1, <64) and candidates (== b1) WITH VALUES into smem.
// Passes 2-4 refine threshold in smem; survivors appended from smem; softmax
// from smem. Fallback to full sweeps if candidates > 512. Exact rank-64 and
// tie semantics preserved.
// ---------------------------------------------------------------------------
#define CANDMAX 512
struct SelSmem {
    int hist[8][256];              // 8 KB
    unsigned short sidx[8][512];   // 8 KB survivor indices
    float sval[8][512];            // 16 KB survivor scores -> probs
    unsigned short cidx[8][CANDMAX]; // 8 KB candidate indices
    unsigned cval[8][CANDMAX];     // 16 KB candidate values
};

__global__ void __launch_bounds__(256, 4)
select_kernel(const unsigned* __restrict__ gsu, const float* __restrict__ V,
              float* __restrict__ Y)
{
    extern __shared__ unsigned char raw[];
    SelSmem* S = reinterpret_cast<SelSmem*>(raw);

    int warp = threadIdx.x >> 5;
    int lane = threadIdx.x & 31;
    unsigned ltmask = (1u << lane) - 1u;

    int bh = blockIdx.y;
    int qi = ((int)gridDim.x - 1 - (int)blockIdx.x) * 8 + warp;  // long rows first
    int n = qi + 1;

    const unsigned* su = gsu + (size_t)(bh * Tc + qi) * Tc;
    const float* Vb = V + (size_t)bh * Tc * HDc;
    int* hist = S->hist[warp];
    unsigned short* sidx = S->sidx[warp];
    float* sval = S->sval[warp];

    int m = 0;
    unsigned umax = 0u;

    if (n <= TOPKc) {
        // all keys survive
        for (int k = lane; k < n; k += 32) {
            unsigned u = su[k];
            umax = max(umax, u);
            sidx[k] = (unsigned short)k;
            sval[k] = u2f(u);
        }
        m = n;
    } else {
        int nvec = n >> 7;           // 128-key groups
        // ---- sweep 1: top-byte histogram + max (vectorized)
        #pragma unroll
        for (int b = lane; b < 256; b += 32) hist[b] = 0;
        __syncwarp();
        const uint4* su4 = reinterpret_cast<const uint4*>(su);
        for (int g = 0; g < nvec; g++) {
            uint4 u = su4[g * 32 + lane];
            atomicAdd(&hist[u.x >> 24], 1);
            atomicAdd(&hist[u.y >> 24], 1);
            atomicAdd(&hist[u.z >> 24], 1);
            atomicAdd(&hist[u.w >> 24], 1);
            umax = max(max(max(u.x, u.y), u.z), max(umax, u.w));
        }
        for (int k = nvec * 128 + lane; k < n; k += 32) {
            unsigned u = su[k];
            atomicAdd(&hist[u >> 24], 1);
            umax = max(umax, u);
        }
        __syncwarp();
        int res = radix_pick(hist, TOPKc, lane);
        unsigned b1 = (unsigned)(res >> 16);
        int need = res & 0xffff;

        // ---- sweep 2: compact keeps + candidates (with values)
        unsigned short* cidx = S->cidx[warp];
        unsigned* cval = S->cval[warp];
        int c = 0;
        for (int g = 0; g < nvec; g++) {
            uint4 u = su4[g * 32 + lane];
            int kb = g * 128 + lane * 4;
            unsigned uu[4] = {u.x, u.y, u.z, u.w};
            #pragma unroll
            for (int s = 0; s < 4; s++) {
                unsigned b = uu[s] >> 24;
                bool kd = b > b1, cdt = b == b1;
                unsigned bk = __ballot_sync(0xffffffffu, kd);
                if (kd) {
                    int p = m + __popc(bk & ltmask);
                    sidx[p] = (unsigned short)(kb + s);
                    sval[p] = u2f(uu[s]);
                }
                m += __popc(bk);
                unsigned bc = __ballot_sync(0xffffffffu, cdt);
                if (cdt) {
                    int p = c + __popc(bc & ltmask);
                    if (p < CANDMAX) {
                        cidx[p] = (unsigned short)(kb + s);
                        cval[p] = uu[s];
                    }
                }
                c += __popc(bc);
            }
        }
        for (int k0 = nvec * 128; k0 < n; k0 += 32) {
            int k = k0 + lane;
            bool a = k < n;
            unsigned u = a ? su[k] : 0u;
            unsigned b = u >> 24;
            bool kd = a && b > b1, cdt = a && b == b1;
            unsigned bk = __ballot_sync(0xffffffffu, kd);
            if (kd) {
                int p = m + __popc(bk & ltmask);
                sidx[p] = (unsigned short)k;
                sval[p] = u2f(u);
            }
            m += __popc(bk);
            unsigned bc = __ballot_sync(0xffffffffu, cdt);
            if (cdt) {
                int p = c + __popc(bc & ltmask);
                if (p < CANDMAX) {
                    cidx[p] = (unsigned short)k;
                    cval[p] = u;
                }
            }
            c += __popc(bc);
        }
        __syncwarp();

        unsigned pref = b1 << 24;
        if (c <= CANDMAX) {
            // refine threshold over smem candidates (passes 2-4)
            #pragma unroll 1
            for (int by = 2; by >= 0; --by) {
                int sh = by * 8;
                #pragma unroll
                for (int b = lane; b < 256; b += 32) hist[b] = 0;
                __syncwarp();
                unsigned hp = pref >> (sh + 8);
                for (int j = lane; j < c; j += 32) {
                    unsigned u = cval[j];
                    if ((u >> (sh + 8)) == hp)
                        atomicAdd(&hist[(u >> sh) & 255u], 1);
                }
                __syncwarp();
                int r2 = radix_pick(hist, need, lane);
                pref |= (unsigned)(r2 >> 16) << sh;
                need = r2 & 0xffff;
            }
            unsigned thrU = pref;
            // append surviving candidates from smem
            for (int j0 = 0; j0 < c; j0 += 32) {
                int j = j0 + lane;
                bool a = j < c;
                unsigned v = a ? cval[j] : 0u;
                bool keep = a && v >= thrU;
                unsigned bal = __ballot_sync(0xffffffffu, keep);
                if (keep) {
                    int p = m + __popc(bal & ltmask);
                    if (p < 512) { sidx[p] = cidx[j]; sval[p] = u2f(v); }
                }
                m += __popc(bal);
            }
        } else {
            // fallback: full-array passes 2-4 + full recompaction
            #pragma unroll 1
            for (int by = 2; by >= 0; --by) {
                int sh = by * 8;
                #pragma unroll
                for (int b = lane; b < 256; b += 32) hist[b] = 0;
                __syncwarp();
                unsigned hp = pref >> (sh + 8);
                for (int k = lane; k < n; k += 32) {
                    unsigned u = su[k];
                    if ((u >> (sh + 8)) == hp)
                        atomicAdd(&hist[(u >> sh) & 255u], 1);
                }
                __syncwarp();
                int r2 = radix_pick(hist, need, lane);
                pref |= (unsigned)(r2 >> 16) << sh;
                need = r2 & 0xffff;
            }
            unsigned thrU = pref;
            m = 0;
            for (int k0 = 0; k0 < n; k0 += 32) {
                int k = k0 + lane;
                bool a = k < n;
                unsigned u = a ? su[k] : 0u;
                bool keep = a && u >= thrU;
                unsigned bal = __ballot_sync(0xffffffffu, keep);
                if (keep) {
                    int p = m + __popc(bal & ltmask);
                    if (p < 512) { sidx[p] = (unsigned short)k; sval[p] = u2f(u); }
                }
                m += __popc(bal);
            }
        }
    }
    if (m > 512) m = 512;
    #pragma unroll
    for (int off = 16; off; off >>= 1)
        umax = max(umax, __shfl_xor_sync(0xffffffffu, umax, off));
    __syncwarp();

    // ---- softmax over survivors (sval -> probs in place)
    float maxf = u2f(umax);
    float lsum = 0.f;
    for (int j = lane; j < m; j += 32) {
        float p = __expf(sval[j] - maxf);
        sval[j] = p;
        lsum += p;
    }
    __syncwarp();
    #pragma unroll
    for (int off = 16; off; off >>= 1) lsum += __shfl_xor_sync(0xffffffffu, lsum, off);
    float rinv = 1.0f / lsum;

    // ---- sparse PV
    const float2* V2 = reinterpret_cast<const float2*>(Vb);
    float2 y = make_float2(0.f, 0.f);
    int j = 0;
    for (; j + 4 <= m; j += 4) {
        int k0 = sidx[j + 0], k1 = sidx[j + 1], k2 = sidx[j + 2], k3 = sidx[j + 3];
        float p0 = sval[j + 0], p1 = sval[j + 1], p2 = sval[j + 2], p3 = sval[j + 3];
        float2 v0 = V2[(size_t)k0 * 32 + lane];
        float2 v1 = V2[(size_t)k1 * 32 + lane];
        float2 v2 = V2[(size_t)k2 * 32 + lane];
        float2 v3 = V2[(size_t)k3 * 32 + lane];
        y.x += p0 * v0.x + p1 * v1.x + p2 * v2.x + p3 * v3.x;
        y.y += p0 * v0.y + p1 * v1.y + p2 * v2.y + p3 * v3.y;
    }
    for (; j < m; j++) {
        int k = sidx[j];
        float p = sval[j];
        float2 v = V2[(size_t)k * 32 + lane];
        y.x += p * v.x; y.y += p * v.y;
    }
    int b = bh >> 3, h = bh & 7;
    *reinterpret_cast<float2*>(Y + (size_t)(b * Tc + qi) * Cc + h * HDc + lane * 2) =
        make_float2(y.x * rinv, y.y * rinv);
}

// ---------------------------------------------------------------------------
extern "C" void kernel_launch(void* const* d_in, const int* in_sizes, int n_in,
                              void* d_out, int out_size)
{
    const float* q  = (const float*)d_in[0];
    const float* Wq = (const float*)d_in[2];
    const float* bq = (const float*)d_in[3];
    const float* Wk = (const float*)d_in[4];
    const float* bk = (const float*)d_in[5];
    const float* Wv = (const float*)d_in[6];
    const float* bv = (const float*)d_in[7];
    const float* Wp = (const float*)d_in[8];
    const float* bp = (const float*)d_in[9];

    float *Qh, *Kh, *Vh, *Yb;
    unsigned* SU;
    cudaGetSymbolAddress((void**)&Qh, g_Qh);
    cudaGetSymbolAddress((void**)&Kh, g_Kh);
    cudaGetSymbolAddress((void**)&Vh, g_Vh);
    cudaGetSymbolAddress((void**)&Yb, g_Y);
    cudaGetSymbolAddress((void**)&SU, g_SU);

    cudaFuncSetAttribute(select_kernel, cudaFuncAttributeMaxDynamicSharedMemorySize,
                         (int)sizeof(SelSmem));

    qkv_kernel<<<dim3(Cc / 128, Mr / 128, 3), 256>>>(q, Wq, bq, Wk, bk, Wv, bv, Qh, Kh, Vh);
    score_kernel<<<dim3(Tc / 128, Tc / 128, BHc), 256>>>(Qh, Kh, SU);
    select_kernel<<<dim3(Tc / 8, BHc), 256, sizeof(SelSmem)>>>(SU, Vh, Yb);
    sgemm_kernel<<<dim3(Cc / 128, Mr / 128), 256>>>(Yb, Wp, bp, (float*)d_out);
}

// round 15
// speedup vs baseline: 1.0687x; 1.0687x over previous
#include <cuda_runtime.h>

#define Bc 2
#define Tc 2048
#define Cc 512
#define Hc 8
#define HDc 64
#define TOPKc 64
#define BHc (Bc*Hc)
#define Mr (Bc*Tc)

// Scratch (device globals; allocations forbidden)
__device__ float g_Qh[BHc*Tc*HDc];
__device__ float g_Kh[BHc*Tc*HDc];
__device__ float g_Vh[BHc*Tc*HDc];
__device__ float g_Y [Bc*Tc*Cc];
__device__ unsigned g_SU[(size_t)BHc*Tc*Tc];   // scores as ordered uints

// ---------------------------------------------------------------------------
// helpers
// ---------------------------------------------------------------------------
__device__ __forceinline__ unsigned f2u(float f) {
    unsigned b = __float_as_uint(f);
    return b ^ ((unsigned)((int)b >> 31) | 0x80000000u);
}
__device__ __forceinline__ float u2f(unsigned u) {
    unsigned b = (u & 0x80000000u) ? (u ^ 0x80000000u) : ~u;
    return __uint_as_float(b);
}

// pick bin containing rank `need` scanning 255..0; returns (byte<<16)|rem_need
__device__ __forceinline__ int radix_pick(const int* hist, int need, int lane) {
    int s = 0;
    #pragma unroll
    for (int j = 0; j < 8; j++) s += hist[255 - lane * 8 - j];
    int cum = s;
    #pragma unroll
    for (int off = 1; off < 32; off <<= 1) {
        int v = __shfl_up_sync(0xffffffffu, cum, off);
        if (lane >= off) cum += v;
    }
    unsigned bal = __ballot_sync(0xffffffffu, cum >= need);
    int selL = __ffs(bal) - 1;
    int above = __shfl_sync(0xffffffffu, cum - s, selL);
    int sneed = need - above;
    int res = 0;
    if (lane == selL) {
        int c = 0;
        #pragma unroll 1
        for (int j = 0; j < 8; j++) {
            int b = 255 - selL * 8 - j;
            int h = hist[b];
            if (c + h >= sneed) { res = (b << 16) | (sneed - c); break; }
            c += h;
        }
    }
    return __shfl_sync(0xffffffffu, res, selL);
}

// ---------------------------------------------------------------------------
// Fused QKV GEMM (round-8 exact, measured 157us).
// ---------------------------------------------------------------------------
__global__ void __launch_bounds__(256, 2)
qkv_kernel(const float* __restrict__ A,
           const float* __restrict__ Wq, const float* __restrict__ bq,
           const float* __restrict__ Wk, const float* __restrict__ bk,
           const float* __restrict__ Wv, const float* __restrict__ bv,
           float* __restrict__ Qh, float* __restrict__ Kh, float* __restrict__ Vh)
{
    int z = blockIdx.z;
    const float* W    = (z == 0) ? Wq : (z == 1) ? Wk : Wv;
    const float* bias = (z == 0) ? bq : (z == 1) ? bk : bv;
    float* out        = (z == 0) ? Qh : (z == 1) ? Kh : Vh;

    __shared__ float As[2][8][128];
    __shared__ float Bs[2][8][128];

    int tid = threadIdx.x;
    int bm = blockIdx.y * 128;
    int bn = blockIdx.x * 128;
    int ty = tid >> 4;
    int tx = tid & 15;

    int arow = tid >> 1;
    int akq  = (tid & 1) * 4;
    int brow = tid >> 5;
    int bcol = (tid & 31) * 4;

    const float* Ag = A + (size_t)(bm + arow) * Cc + akq;
    const float* Wg = W + (size_t)brow * Cc + bn + bcol;

    float acc[8][8];
    #pragma unroll
    for (int i = 0; i < 8; i++)
        #pragma unroll
        for (int j = 0; j < 8; j++) acc[i][j] = 0.f;

    {
        float4 av = *reinterpret_cast<const float4*>(Ag);
        float4 bv4 = *reinterpret_cast<const float4*>(Wg);
        As[0][akq + 0][arow] = av.x;
        As[0][akq + 1][arow] = av.y;
        As[0][akq + 2][arow] = av.z;
        As[0][akq + 3][arow] = av.w;
        *reinterpret_cast<float4*>(&Bs[0][brow][bcol]) = bv4;
    }
    __syncthreads();

    #pragma unroll 1
    for (int kb = 0; kb < 64; kb++) {
        int cur = kb & 1;
        float4 an, bnv;
        if (kb < 63) {
            an  = *reinterpret_cast<const float4*>(Ag + (kb + 1) * 8);
            bnv = *reinterpret_cast<const float4*>(Wg + (size_t)(kb + 1) * 8 * Cc);
        }
        #pragma unroll
        for (int k = 0; k < 8; k++) {
            float4 a0 = *reinterpret_cast<const float4*>(&As[cur][k][ty * 4]);
            float4 a1 = *reinterpret_cast<const float4*>(&As[cur][k][64 + ty * 4]);
            float4 b0 = *reinterpret_cast<const float4*>(&Bs[cur][k][tx * 4]);
            float4 b1 = *reinterpret_cast<const float4*>(&Bs[cur][k][64 + tx * 4]);
            float a[8] = {a0.x, a0.y, a0.z, a0.w, a1.x, a1.y, a1.z, a1.w};
            float b[8] = {b0.x, b0.y, b0.z, b0.w, b1.x, b1.y, b1.z, b1.w};
            #pragma unroll
            for (int i = 0; i < 8; i++)
                #pragma unroll
                for (int j = 0; j < 8; j++)
                    acc[i][j] += a[i] * b[j];
        }
        if (kb < 63) {
            int nxt = cur ^ 1;
            As[nxt][akq + 0][arow] = an.x;
            As[nxt][akq + 1][arow] = an.y;
            As[nxt][akq + 2][arow] = an.z;
            As[nxt][akq + 3][arow] = an.w;
            *reinterpret_cast<float4*>(&Bs[nxt][brow][bcol]) = bnv;
            __syncthreads();
        }
    }

    float4 bia0 = *reinterpret_cast<const float4*>(bias + bn + tx * 4);
    float4 bia1 = *reinterpret_cast<const float4*>(bias + bn + 64 + tx * 4);
    #pragma unroll
    for (int i = 0; i < 8; i++) {
        int r = (i < 4) ? (ty * 4 + i) : (64 + ty * 4 + (i - 4));
        int mrow = bm + r;
        int b = mrow >> 11;
        int t = mrow & (Tc - 1);
        float4 o0 = make_float4(acc[i][0] + bia0.x, acc[i][1] + bia0.y,
                                acc[i][2] + bia0.z, acc[i][3] + bia0.w);
        float4 o1 = make_float4(acc[i][4] + bia1.x, acc[i][5] + bia1.y,
                                acc[i][6] + bia1.z, acc[i][7] + bia1.w);
        if (z == 2) {
            float ss0 = o0.x*o0.x + o0.y*o0.y + o0.z*o0.z + o0.w*o0.w;
            float ss1 = o1.x*o1.x + o1.y*o1.y + o1.z*o1.z + o1.w*o1.w;
            #pragma unroll
            for (int off = 8; off; off >>= 1) {
                ss0 += __shfl_xor_sync(0xffffffffu, ss0, off);
                ss1 += __shfl_xor_sync(0xffffffffu, ss1, off);
            }
            float sc0 = 1.0f / fmaxf(sqrtf(ss0), 1e-12f);
            float sc1 = 1.0f / fmaxf(sqrtf(ss1), 1e-12f);
            o0.x *= sc0; o0.y *= sc0; o0.z *= sc0; o0.w *= sc0;
            o1.x *= sc1; o1.y *= sc1; o1.z *= sc1; o1.w *= sc1;
        }
        int n0 = bn + tx * 4;       int h0 = n0 >> 6, d0 = n0 & 63;
        int n1 = bn + 64 + tx * 4;  int h1 = n1 >> 6, d1 = n1 & 63;
        *reinterpret_cast<float4*>(out + ((size_t)((b * Hc + h0) * Tc + t) << 6) + d0) = o0;
        *reinterpret_cast<float4*>(out + ((size_t)((b * Hc + h1) * Tc + t) << 6) + d1) = o1;
    }
}

// ---------------------------------------------------------------------------
// Output projection GEMM (row-major out), r13 exact (measured 63us).
// ---------------------------------------------------------------------------
__global__ void __launch_bounds__(256, 2)
sgemm_kernel(const float* __restrict__ A, const float* __restrict__ W,
             const float* __restrict__ bias, float* __restrict__ out)
{
    __shared__ float As[2][8][128];
    __shared__ float Bs[2][8][128];

    int tid = threadIdx.x;
    int bm = blockIdx.y * 128;
    int bn = blockIdx.x * 128;
    int ty = tid >> 4;
    int tx = tid & 15;

    int arow = tid >> 1;
    int akq  = (tid & 1) * 4;
    int brow = tid >> 5;
    int bcol = (tid & 31) * 4;

    const float* Ag = A + (size_t)(bm + arow) * Cc + akq;
    const float* Wg = W + (size_t)brow * Cc + bn + bcol;

    float acc[8][8];
    #pragma unroll
    for (int i = 0; i < 8; i++)
        #pragma unroll
        for (int j = 0; j < 8; j++) acc[i][j] = 0.f;

    {
        float4 av = *reinterpret_cast<const float4*>(Ag);
        float4 bv4 = *reinterpret_cast<const float4*>(Wg);
        As[0][akq + 0][arow] = av.x;
        As[0][akq + 1][arow] = av.y;
        As[0][akq + 2][arow] = av.z;
        As[0][akq + 3][arow] = av.w;
        *reinterpret_cast<float4*>(&Bs[0][brow][bcol]) = bv4;
    }
    __syncthreads();

    #pragma unroll 1
    for (int kb = 0; kb < 64; kb++) {
        int cur = kb & 1;
        float4 an, bnv;
        if (kb < 63) {
            an  = *reinterpret_cast<const float4*>(Ag + (kb + 1) * 8);
            bnv = *reinterpret_cast<const float4*>(Wg + (size_t)(kb + 1) * 8 * Cc);
        }
        #pragma unroll
        for (int k = 0; k < 8; k++) {
            float4 a0 = *reinterpret_cast<const float4*>(&As[cur][k][ty * 4]);
            float4 a1 = *reinterpret_cast<const float4*>(&As[cur][k][64 + ty * 4]);
            float4 b0 = *reinterpret_cast<const float4*>(&Bs[cur][k][tx * 4]);
            float4 b1 = *reinterpret_cast<const float4*>(&Bs[cur][k][64 + tx * 4]);
            float a[8] = {a0.x, a0.y, a0.z, a0.w, a1.x, a1.y, a1.z, a1.w};
            float b[8] = {b0.x, b0.y, b0.z, b0.w, b1.x, b1.y, b1.z, b1.w};
            #pragma unroll
            for (int i = 0; i < 8; i++)
                #pragma unroll
                for (int j = 0; j < 8; j++)
                    acc[i][j] += a[i] * b[j];
        }
        if (kb < 63) {
            int nxt = cur ^ 1;
            As[nxt][akq + 0][arow] = an.x;
            As[nxt][akq + 1][arow] = an.y;
            As[nxt][akq + 2][arow] = an.z;
            As[nxt][akq + 3][arow] = an.w;
            *reinterpret_cast<float4*>(&Bs[nxt][brow][bcol]) = bnv;
            __syncthreads();
        }
    }

    float4 bia0 = *reinterpret_cast<const float4*>(bias + bn + tx * 4);
    float4 bia1 = *reinterpret_cast<const float4*>(bias + bn + 64 + tx * 4);
    #pragma unroll
    for (int i = 0; i < 8; i++) {
        int r = (i < 4) ? (ty * 4 + i) : (64 + ty * 4 + (i - 4));
        int mrow = bm + r;
        float4 o0 = make_float4(acc[i][0] + bia0.x, acc[i][1] + bia0.y,
                                acc[i][2] + bia0.z, acc[i][3] + bia0.w);
        float4 o1 = make_float4(acc[i][4] + bia1.x, acc[i][5] + bia1.y,
                                acc[i][6] + bia1.z, acc[i][7] + bia1.w);
        *reinterpret_cast<float4*>(out + (size_t)mrow * Cc + bn + tx * 4) = o0;
        *reinterpret_cast<float4*>(out + (size_t)mrow * Cc + bn + 64 + tx * 4) = o1;
    }
}

// ---------------------------------------------------------------------------
// Score GEMM (r13 exact): su[q][k] = f2u((Q.K)*0.125), 128x128 tile/block.
// ---------------------------------------------------------------------------
__global__ void __launch_bounds__(256, 2)
score_kernel(const float* __restrict__ Qh, const float* __restrict__ Kh,
             unsigned* __restrict__ gsu)
{
    if (blockIdx.x > blockIdx.y) return;
    int bh = blockIdx.z;
    int q0 = blockIdx.y * 128;
    int k0 = blockIdx.x * 128;

    __shared__ float As[2][8][128];
    __shared__ float Bs[2][8][128];

    int tid = threadIdx.x;
    int ty = tid >> 4;
    int tx = tid & 15;

    int arow = tid >> 1;
    int akq  = (tid & 1) * 4;

    const float* Ag = Qh + ((size_t)(bh * Tc + q0) + arow) * HDc + akq;
    const float* Bg = Kh + ((size_t)(bh * Tc + k0) + arow) * HDc + akq;

    float acc[8][8];
    #pragma unroll
    for (int i = 0; i < 8; i++)
        #pragma unroll
        for (int j = 0; j < 8; j++) acc[i][j] = 0.f;

    {
        float4 av = *reinterpret_cast<const float4*>(Ag);
        float4 bv = *reinterpret_cast<const float4*>(Bg);
        As[0][akq + 0][arow] = av.x;
        As[0][akq + 1][arow] = av.y;
        As[0][akq + 2][arow] = av.z;
        As[0][akq + 3][arow] = av.w;
        Bs[0][akq + 0][arow] = bv.x;
        Bs[0][akq + 1][arow] = bv.y;
        Bs[0][akq + 2][arow] = bv.z;
        Bs[0][akq + 3][arow] = bv.w;
    }
    __syncthreads();

    #pragma unroll 1
    for (int kb = 0; kb < 8; kb++) {
        int cur = kb & 1;
        float4 an, bn;
        if (kb < 7) {
            an = *reinterpret_cast<const float4*>(Ag + (kb + 1) * 8);
            bn = *reinterpret_cast<const float4*>(Bg + (kb + 1) * 8);
        }
        #pragma unroll
        for (int k = 0; k < 8; k++) {
            float4 a0 = *reinterpret_cast<const float4*>(&As[cur][k][ty * 4]);
            float4 a1 = *reinterpret_cast<const float4*>(&As[cur][k][64 + ty * 4]);
            float4 b0 = *reinterpret_cast<const float4*>(&Bs[cur][k][tx * 4]);
            float4 b1 = *reinterpret_cast<const float4*>(&Bs[cur][k][64 + tx * 4]);
            float a[8] = {a0.x, a0.y, a0.z, a0.w, a1.x, a1.y, a1.z, a1.w};
            float b[8] = {b0.x, b0.y, b0.z, b0.w, b1.x, b1.y, b1.z, b1.w};
            #pragma unroll
            for (int i = 0; i < 8; i++)
                #pragma unroll
                for (int j = 0; j < 8; j++)
                    acc[i][j] += a[i] * b[j];
        }
        if (kb < 7) {
            int nxt = cur ^ 1;
            As[nxt][akq + 0][arow] = an.x;
            As[nxt][akq + 1][arow] = an.y;
            As[nxt][akq + 2][arow] = an.z;
            As[nxt][akq + 3][arow] = an.w;
            Bs[nxt][akq + 0][arow] = bn.x;
            Bs[nxt][akq + 1][arow] = bn.y;
            Bs[nxt][akq + 2][arow] = bn.z;
            Bs[nxt][akq + 3][arow] = bn.w;
            __syncthreads();
        }
    }

    #pragma unroll
    for (int i = 0; i < 8; i++) {
        int r = (i < 4) ? (ty * 4 + i) : (64 + ty * 4 + (i - 4));
        unsigned* dst = gsu + (size_t)(bh * Tc + q0 + r) * Tc + k0;
        uint4 u0, u1;
        u0.x = f2u(acc[i][0] * 0.125f); u0.y = f2u(acc[i][1] * 0.125f);
        u0.z = f2u(acc[i][2] * 0.125f); u0.w = f2u(acc[i][3] * 0.125f);
        u1.x = f2u(acc[i][4] * 0.125f); u1.y = f2u(acc[i][5] * 0.125f);
        u1.z = f2u(acc[i][6] * 0.125f); u1.w = f2u(acc[i][7] * 0.125f);
        *reinterpret_cast<uint4*>(dst + tx * 4)      = u0;
        *reinterpret_cast<uint4*>(dst + 64 + tx * 4) = u1;
    }
}

// ---------------------------------------------------------------------------
// Select kernel v3: per-lane top-2 preselection.
// Sweep 1 (uint4, pure ALU): per-lane top-2 + row max. t0 = warp-min of the
// 64-value union -> provable lower bound on the rank-64 value.
// Sweep 2: ballot-compact candidates {u >= t0} (typically 64-300) into smem.
// Exact rank-64 via 4-pass radix over smem candidates (tiny). Softmax/PV over
// candidates with p=0 for dropped ones (identical semantics). Fallback to
// full-array radix if candidates overflow. 32 KB smem -> 6 blocks/SM.
// ---------------------------------------------------------------------------
#define CMAX 512
struct SelSmem {
    int hist[8][256];                // 8 KB
    unsigned short cidx[8][CMAX];    // 8 KB candidate indices
    unsigned cval[8][CMAX];          // 16 KB candidate values (reused as probs)
};

__global__ void __launch_bounds__(256, 6)
select_kernel(const unsigned* __restrict__ gsu, const float* __restrict__ V,
              float* __restrict__ Y)
{
    extern __shared__ unsigned char raw[];
    SelSmem* S = reinterpret_cast<SelSmem*>(raw);

    int warp = threadIdx.x >> 5;
    int lane = threadIdx.x & 31;
    unsigned ltmask = (1u << lane) - 1u;

    int bh = blockIdx.y;
    int qi = ((int)gridDim.x - 1 - (int)blockIdx.x) * 8 + warp;  // long rows first
    int n = qi + 1;

    const unsigned* su = gsu + (size_t)(bh * Tc + qi) * Tc;
    const float* Vb = V + (size_t)bh * Tc * HDc;
    int* hist = S->hist[warp];
    unsigned short* cidx = S->cidx[warp];
    unsigned* cval = S->cval[warp];

    int c = 0;
    unsigned umax = 0u;
    unsigned thrU = 0u;

    if (n <= TOPKc) {
        for (int k = lane; k < n; k += 32) {
            unsigned u = su[k];
            umax = max(umax, u);
            cidx[k] = (unsigned short)k;
            cval[k] = u;
        }
        c = n;
        #pragma unroll
        for (int off = 16; off; off >>= 1)
            umax = max(umax, __shfl_xor_sync(0xffffffffu, umax, off));
    } else {
        // ---- sweep 1: per-lane top-2 (v1 >= v2) + max, uint4 vectorized
        unsigned v1 = 0u, v2 = 0u;
        int nvec = n >> 7;
        const uint4* su4 = reinterpret_cast<const uint4*>(su);
        for (int g = 0; g < nvec; g++) {
            uint4 u = su4[g * 32 + lane];
            unsigned uu[4] = {u.x, u.y, u.z, u.w};
            #pragma unroll
            for (int s = 0; s < 4; s++) {
                unsigned x = uu[s];
                if (x > v1) { v2 = v1; v1 = x; }
                else if (x > v2) { v2 = x; }
            }
        }
        for (int k = nvec * 128 + lane; k < n; k += 32) {
            unsigned x = su[k];
            if (x > v1) { v2 = v1; v1 = x; }
            else if (x > v2) { v2 = x; }
        }
        umax = v1;
        unsigned t0 = v2;
        #pragma unroll
        for (int off = 16; off; off >>= 1) {
            umax = max(umax, __shfl_xor_sync(0xffffffffu, umax, off));
            t0   = min(t0,   __shfl_xor_sync(0xffffffffu, t0,   off));
        }

        // ---- sweep 2: compact candidates u >= t0 (ordered, r13-style)
        #pragma unroll 1
        for (int k0 = 0; k0 < n; k0 += 32) {
            int k = k0 + lane;
            bool a = k < n;
            unsigned u = a ? su[k] : 0u;
            bool keep = a && (u >= t0);
            unsigned bal = __ballot_sync(0xffffffffu, keep);
            if (keep) {
                int p = c + __popc(bal & ltmask);
                if (p < CMAX) { cidx[p] = (unsigned short)k; cval[p] = u; }
            }
            c += __popc(bal);
        }
        __syncwarp();

        if (c <= CMAX) {
            // ---- exact rank-64: 4-pass byte radix over smem candidates
            unsigned pref = 0u; int need = TOPKc;
            #pragma unroll 1
            for (int by = 3; by >= 0; --by) {
                int sh = by * 8;
                #pragma unroll
                for (int b = lane; b < 256; b += 32) hist[b] = 0;
                __syncwarp();
                unsigned hp = (by < 3) ? (pref >> (sh + 8)) : 0u;
                for (int j = lane; j < c; j += 32) {
                    unsigned u = cval[j];
                    if (by == 3 || (u >> (sh + 8)) == hp)
                        atomicAdd(&hist[(u >> sh) & 255u], 1);
                }
                __syncwarp();
                int r2 = radix_pick(hist, need, lane);
                pref |= (unsigned)(r2 >> 16) << sh;
                need = r2 & 0xffff;
            }
            thrU = pref;
        } else {
            // ---- fallback: full-array radix (r13 form), then recompact
            unsigned pref = 0u; int need = TOPKc;
            #pragma unroll 1
            for (int by = 3; by >= 0; --by) {
                int sh = by * 8;
                #pragma unroll
                for (int b = lane; b < 256; b += 32) hist[b] = 0;
                __syncwarp();
                unsigned hp = (by < 3) ? (pref >> (sh + 8)) : 0u;
                for (int k = lane; k < n; k += 32) {
                    unsigned u = su[k];
                    if (by == 3 || (u >> (sh + 8)) == hp)
                        atomicAdd(&hist[(u >> sh) & 255u], 1);
                }
                __syncwarp();
                int r2 = radix_pick(hist, need, lane);
                pref |= (unsigned)(r2 >> 16) << sh;
                need = r2 & 0xffff;
            }
            thrU = pref;
            c = 0;
            #pragma unroll 1
            for (int k0 = 0; k0 < n; k0 += 32) {
                int k = k0 + lane;
                bool a = k < n;
                unsigned u = a ? su[k] : 0u;
                bool keep = a && (u >= thrU);
                unsigned bal = __ballot_sync(0xffffffffu, keep);
                if (keep) {
                    int p = c + __popc(bal & ltmask);
                    if (p < CMAX) { cidx[p] = (unsigned short)k; cval[p] = u; }
                }
                c += __popc(bal);
            }
            __syncwarp();
        }
    }
    if (c > CMAX) c = CMAX;

    // ---- softmax over candidates (dropped ones get p = 0 exactly)
    float maxf = u2f(umax);
    float lsum = 0.f;
    for (int j = lane; j < c; j += 32) {
        unsigned u = cval[j];
        float p = (u >= thrU) ? __expf(u2f(u) - maxf) : 0.f;
        cval[j] = __float_as_uint(p);
        lsum += p;
    }
    __syncwarp();
    #pragma unroll
    for (int off = 16; off; off >>= 1) lsum += __shfl_xor_sync(0xffffffffu, lsum, off);
    float rinv = 1.0f / lsum;

    // ---- sparse PV over candidates
    const float2* V2 = reinterpret_cast<const float2*>(Vb);
    float2 y = make_float2(0.f, 0.f);
    int j = 0;
    for (; j + 4 <= c; j += 4) {
        int k0 = cidx[j + 0], k1 = cidx[j + 1], k2 = cidx[j + 2], k3 = cidx[j + 3];
        float p0 = __uint_as_float(cval[j + 0]);
        float p1 = __uint_as_float(cval[j + 1]);
        float p2 = __uint_as_float(cval[j + 2]);
        float p3 = __uint_as_float(cval[j + 3]);
        float2 v0 = V2[(size_t)k0 * 32 + lane];
        float2 v1 = V2[(size_t)k1 * 32 + lane];
        float2 v2 = V2[(size_t)k2 * 32 + lane];
        float2 v3 = V2[(size_t)k3 * 32 + lane];
        y.x += p0 * v0.x + p1 * v1.x + p2 * v2.x + p3 * v3.x;
        y.y += p0 * v0.y + p1 * v1.y + p2 * v2.y + p3 * v3.y;
    }
    for (; j < c; j++) {
        int k = cidx[j];
        float p = __uint_as_float(cval[j]);
        float2 v = V2[(size_t)k * 32 + lane];
        y.x += p * v.x; y.y += p * v.y;
    }
    int b = bh >> 3, h = bh & 7;
    *reinterpret_cast<float2*>(Y + (size_t)(b * Tc + qi) * Cc + h * HDc + lane * 2) =
        make_float2(y.x * rinv, y.y * rinv);
}

// ---------------------------------------------------------------------------
extern "C" void kernel_launch(void* const* d_in, const int* in_sizes, int n_in,
                              void* d_out, int out_size)
{
    const float* q  = (const float*)d_in[0];
    const float* Wq = (const float*)d_in[2];
    const float* bq = (const float*)d_in[3];
    const float* Wk = (const float*)d_in[4];
    const float* bk = (const float*)d_in[5];
    const float* Wv = (const float*)d_in[6];
    const float* bv = (const float*)d_in[7];
    const float* Wp = (const float*)d_in[8];
    const float* bp = (const float*)d_in[9];

    float *Qh, *Kh, *Vh, *Yb;
    unsigned* SU;
    cudaGetSymbolAddress((void**)&Qh, g_Qh);
    cudaGetSymbolAddress((void**)&Kh, g_Kh);
    cudaGetSymbolAddress((void**)&Vh, g_Vh);
    cudaGetSymbolAddress((void**)&Yb, g_Y);
    cudaGetSymbolAddress((void**)&SU, g_SU);

    cudaFuncSetAttribute(select_kernel, cudaFuncAttributeMaxDynamicSharedMemorySize,
                         (int)sizeof(SelSmem));

    qkv_kernel<<<dim3(Cc / 128, Mr / 128, 3), 256>>>(q, Wq, bq, Wk, bk, Wv, bv, Qh, Kh, Vh);
    score_kernel<<<dim3(Tc / 128, Tc / 128, BHc), 256>>>(Qh, Kh, SU);
    select_kernel<<<dim3(Tc / 8, BHc), 256, sizeof(SelSmem)>>>(SU, Vh, Yb);
    sgemm_kernel<<<dim3(Cc / 128, Mr / 128), 256>>>(Yb, Wp, bp, (float*)d_out);
}

// round 16
// speedup vs baseline: 1.0920x; 1.0218x over previous
#include <cuda_runtime.h>

#define Bc 2
#define Tc 2048
#define Cc 512
#define Hc 8
#define HDc 64
#define TOPKc 64
#define BHc (Bc*Hc)
#define Mr (Bc*Tc)

// Scratch (device globals; allocations forbidden)
__device__ float g_Qh[BHc*Tc*HDc];
__device__ float g_Kh[BHc*Tc*HDc];
__device__ float g_Vh[BHc*Tc*HDc];
__device__ float g_Y [Bc*Tc*Cc];
__device__ unsigned g_SU[(size_t)BHc*Tc*Tc];   // scores as ordered uints

// ---------------------------------------------------------------------------
// helpers
// ---------------------------------------------------------------------------
__device__ __forceinline__ unsigned f2u(float f) {
    unsigned b = __float_as_uint(f);
    return b ^ ((unsigned)((int)b >> 31) | 0x80000000u);
}
__device__ __forceinline__ float u2f(unsigned u) {
    unsigned b = (u & 0x80000000u) ? (u ^ 0x80000000u) : ~u;
    return __uint_as_float(b);
}

// ---------------------------------------------------------------------------
// Fused QKV GEMM (round-8 exact, measured 157us).
// ---------------------------------------------------------------------------
__global__ void __launch_bounds__(256, 2)
qkv_kernel(const float* __restrict__ A,
           const float* __restrict__ Wq, const float* __restrict__ bq,
           const float* __restrict__ Wk, const float* __restrict__ bk,
           const float* __restrict__ Wv, const float* __restrict__ bv,
           float* __restrict__ Qh, float* __restrict__ Kh, float* __restrict__ Vh)
{
    int z = blockIdx.z;
    const float* W    = (z == 0) ? Wq : (z == 1) ? Wk : Wv;
    const float* bias = (z == 0) ? bq : (z == 1) ? bk : bv;
    float* out        = (z == 0) ? Qh : (z == 1) ? Kh : Vh;

    __shared__ float As[2][8][128];
    __shared__ float Bs[2][8][128];

    int tid = threadIdx.x;
    int bm = blockIdx.y * 128;
    int bn = blockIdx.x * 128;
    int ty = tid >> 4;
    int tx = tid & 15;

    int arow = tid >> 1;
    int akq  = (tid & 1) * 4;
    int brow = tid >> 5;
    int bcol = (tid & 31) * 4;

    const float* Ag = A + (size_t)(bm + arow) * Cc + akq;
    const float* Wg = W + (size_t)brow * Cc + bn + bcol;

    float acc[8][8];
    #pragma unroll
    for (int i = 0; i < 8; i++)
        #pragma unroll
        for (int j = 0; j < 8; j++) acc[i][j] = 0.f;

    {
        float4 av = *reinterpret_cast<const float4*>(Ag);
        float4 bv4 = *reinterpret_cast<const float4*>(Wg);
        As[0][akq + 0][arow] = av.x;
        As[0][akq + 1][arow] = av.y;
        As[0][akq + 2][arow] = av.z;
        As[0][akq + 3][arow] = av.w;
        *reinterpret_cast<float4*>(&Bs[0][brow][bcol]) = bv4;
    }
    __syncthreads();

    #pragma unroll 1
    for (int kb = 0; kb < 64; kb++) {
        int cur = kb & 1;
        float4 an, bnv;
        if (kb < 63) {
            an  = *reinterpret_cast<const float4*>(Ag + (kb + 1) * 8);
            bnv = *reinterpret_cast<const float4*>(Wg + (size_t)(kb + 1) * 8 * Cc);
        }
        #pragma unroll
        for (int k = 0; k < 8; k++) {
            float4 a0 = *reinterpret_cast<const float4*>(&As[cur][k][ty * 4]);
            float4 a1 = *reinterpret_cast<const float4*>(&As[cur][k][64 + ty * 4]);
            float4 b0 = *reinterpret_cast<const float4*>(&Bs[cur][k][tx * 4]);
            float4 b1 = *reinterpret_cast<const float4*>(&Bs[cur][k][64 + tx * 4]);
            float a[8] = {a0.x, a0.y, a0.z, a0.w, a1.x, a1.y, a1.z, a1.w};
            float b[8] = {b0.x, b0.y, b0.z, b0.w, b1.x, b1.y, b1.z, b1.w};
            #pragma unroll
            for (int i = 0; i < 8; i++)
                #pragma unroll
                for (int j = 0; j < 8; j++)
                    acc[i][j] += a[i] * b[j];
        }
        if (kb < 63) {
            int nxt = cur ^ 1;
            As[nxt][akq + 0][arow] = an.x;
            As[nxt][akq + 1][arow] = an.y;
            As[nxt][akq + 2][arow] = an.z;
            As[nxt][akq + 3][arow] = an.w;
            *reinterpret_cast<float4*>(&Bs[nxt][brow][bcol]) = bnv;
            __syncthreads();
        }
    }

    float4 bia0 = *reinterpret_cast<const float4*>(bias + bn + tx * 4);
    float4 bia1 = *reinterpret_cast<const float4*>(bias + bn + 64 + tx * 4);
    #pragma unroll
    for (int i = 0; i < 8; i++) {
        int r = (i < 4) ? (ty * 4 + i) : (64 + ty * 4 + (i - 4));
        int mrow = bm + r;
        int b = mrow >> 11;
        int t = mrow & (Tc - 1);
        float4 o0 = make_float4(acc[i][0] + bia0.x, acc[i][1] + bia0.y,
                                acc[i][2] + bia0.z, acc[i][3] + bia0.w);
        float4 o1 = make_float4(acc[i][4] + bia1.x, acc[i][5] + bia1.y,
                                acc[i][6] + bia1.z, acc[i][7] + bia1.w);
        if (z == 2) {
            float ss0 = o0.x*o0.x + o0.y*o0.y + o0.z*o0.z + o0.w*o0.w;
            float ss1 = o1.x*o1.x + o1.y*o1.y + o1.z*o1.z + o1.w*o1.w;
            #pragma unroll
            for (int off = 8; off; off >>= 1) {
                ss0 += __shfl_xor_sync(0xffffffffu, ss0, off);
                ss1 += __shfl_xor_sync(0xffffffffu, ss1, off);
            }
            float sc0 = 1.0f / fmaxf(sqrtf(ss0), 1e-12f);
            float sc1 = 1.0f / fmaxf(sqrtf(ss1), 1e-12f);
            o0.x *= sc0; o0.y *= sc0; o0.z *= sc0; o0.w *= sc0;
            o1.x *= sc1; o1.y *= sc1; o1.z *= sc1; o1.w *= sc1;
        }
        int n0 = bn + tx * 4;       int h0 = n0 >> 6, d0 = n0 & 63;
        int n1 = bn + 64 + tx * 4;  int h1 = n1 >> 6, d1 = n1 & 63;
        *reinterpret_cast<float4*>(out + ((size_t)((b * Hc + h0) * Tc + t) << 6) + d0) = o0;
        *reinterpret_cast<float4*>(out + ((size_t)((b * Hc + h1) * Tc + t) << 6) + d1) = o1;
    }
}

// ---------------------------------------------------------------------------
// Output projection GEMM: BM=64, BN=128, BK=8, 256 thr, 4x8 micro,
// 3 blocks/SM (256 blocks -> <1 wave at much higher occupancy).
// ---------------------------------------------------------------------------
__global__ void __launch_bounds__(256, 3)
sgemm_kernel(const float* __restrict__ A, const float* __restrict__ W,
             const float* __restrict__ bias, float* __restrict__ out)
{
    __shared__ float As[2][8][64];
    __shared__ float Bs[2][8][128];

    int tid = threadIdx.x;
    int bm = blockIdx.y * 64;
    int bn = blockIdx.x * 128;
    int ty = tid >> 4;            // 0..15 -> rows ty*4..+3
    int tx = tid & 15;            // 0..15 -> cols tx*4, 64+tx*4

    int arow = (tid & 127) >> 1;  // 0..63 (threads 0..127 load A)
    int akq  = (tid & 1) * 4;
    int brow = tid >> 5;
    int bcol = (tid & 31) * 4;

    const float* Ag = A + (size_t)(bm + arow) * Cc + akq;
    const float* Wg = W + (size_t)brow * Cc + bn + bcol;

    float acc[4][8];
    #pragma unroll
    for (int i = 0; i < 4; i++)
        #pragma unroll
        for (int j = 0; j < 8; j++) acc[i][j] = 0.f;

    {
        if (tid < 128) {
            float4 av = *reinterpret_cast<const float4*>(Ag);
            As[0][akq + 0][arow] = av.x;
            As[0][akq + 1][arow] = av.y;
            As[0][akq + 2][arow] = av.z;
            As[0][akq + 3][arow] = av.w;
        }
        float4 bv4 = *reinterpret_cast<const float4*>(Wg);
        *reinterpret_cast<float4*>(&Bs[0][brow][bcol]) = bv4;
    }
    __syncthreads();

    #pragma unroll 1
    for (int kb = 0; kb < 64; kb++) {
        int cur = kb & 1;
        float4 an, bnv;
        if (kb < 63) {
            if (tid < 128)
                an = *reinterpret_cast<const float4*>(Ag + (kb + 1) * 8);
            bnv = *reinterpret_cast<const float4*>(Wg + (size_t)(kb + 1) * 8 * Cc);
        }
        #pragma unroll
        for (int k = 0; k < 8; k++) {
            float4 a0 = *reinterpret_cast<const float4*>(&As[cur][k][ty * 4]);
            float4 b0 = *reinterpret_cast<const float4*>(&Bs[cur][k][tx * 4]);
            float4 b1 = *reinterpret_cast<const float4*>(&Bs[cur][k][64 + tx * 4]);
            float a[4] = {a0.x, a0.y, a0.z, a0.w};
            float b[8] = {b0.x, b0.y, b0.z, b0.w, b1.x, b1.y, b1.z, b1.w};
            #pragma unroll
            for (int i = 0; i < 4; i++)
                #pragma unroll
                for (int j = 0; j < 8; j++)
                    acc[i][j] += a[i] * b[j];
        }
        if (kb < 63) {
            int nxt = cur ^ 1;
            if (tid < 128) {
                As[nxt][akq + 0][arow] = an.x;
                As[nxt][akq + 1][arow] = an.y;
                As[nxt][akq + 2][arow] = an.z;
                As[nxt][akq + 3][arow] = an.w;
            }
            *reinterpret_cast<float4*>(&Bs[nxt][brow][bcol]) = bnv;
            __syncthreads();
        }
    }

    float4 bia0 = *reinterpret_cast<const float4*>(bias + bn + tx * 4);
    float4 bia1 = *reinterpret_cast<const float4*>(bias + bn + 64 + tx * 4);
    #pragma unroll
    for (int i = 0; i < 4; i++) {
        int mrow = bm + ty * 4 + i;
        float4 o0 = make_float4(acc[i][0] + bia0.x, acc[i][1] + bia0.y,
                                acc[i][2] + bia0.z, acc[i][3] + bia0.w);
        float4 o1 = make_float4(acc[i][4] + bia1.x, acc[i][5] + bia1.y,
                                acc[i][6] + bia1.z, acc[i][7] + bia1.w);
        *reinterpret_cast<float4*>(out + (size_t)mrow * Cc + bn + tx * 4) = o0;
        *reinterpret_cast<float4*>(out + (size_t)mrow * Cc + bn + 64 + tx * 4) = o1;
    }
}

// ---------------------------------------------------------------------------
// Score GEMM (r13 exact): su[q][k] = f2u((Q.K)*0.125), 128x128 tile/block.
// ---------------------------------------------------------------------------
__global__ void __launch_bounds__(256, 2)
score_kernel(const float* __restrict__ Qh, const float* __restrict__ Kh,
             unsigned* __restrict__ gsu)
{
    if (blockIdx.x > blockIdx.y) return;
    int bh = blockIdx.z;
    int q0 = blockIdx.y * 128;
    int k0 = blockIdx.x * 128;

    __shared__ float As[2][8][128];
    __shared__ float Bs[2][8][128];

    int tid = threadIdx.x;
    int ty = tid >> 4;
    int tx = tid & 15;

    int arow = tid >> 1;
    int akq  = (tid & 1) * 4;

    const float* Ag = Qh + ((size_t)(bh * Tc + q0) + arow) * HDc + akq;
    const float* Bg = Kh + ((size_t)(bh * Tc + k0) + arow) * HDc + akq;

    float acc[8][8];
    #pragma unroll
    for (int i = 0; i < 8; i++)
        #pragma unroll
        for (int j = 0; j < 8; j++) acc[i][j] = 0.f;

    {
        float4 av = *reinterpret_cast<const float4*>(Ag);
        float4 bv = *reinterpret_cast<const float4*>(Bg);
        As[0][akq + 0][arow] = av.x;
        As[0][akq + 1][arow] = av.y;
        As[0][akq + 2][arow] = av.z;
        As[0][akq + 3][arow] = av.w;
        Bs[0][akq + 0][arow] = bv.x;
        Bs[0][akq + 1][arow] = bv.y;
        Bs[0][akq + 2][arow] = bv.z;
        Bs[0][akq + 3][arow] = bv.w;
    }
    __syncthreads();

    #pragma unroll 1
    for (int kb = 0; kb < 8; kb++) {
        int cur = kb & 1;
        float4 an, bn;
        if (kb < 7) {
            an = *reinterpret_cast<const float4*>(Ag + (kb + 1) * 8);
            bn = *reinterpret_cast<const float4*>(Bg + (kb + 1) * 8);
        }
        #pragma unroll
        for (int k = 0; k < 8; k++) {
            float4 a0 = *reinterpret_cast<const float4*>(&As[cur][k][ty * 4]);
            float4 a1 = *reinterpret_cast<const float4*>(&As[cur][k][64 + ty * 4]);
            float4 b0 = *reinterpret_cast<const float4*>(&Bs[cur][k][tx * 4]);
            float4 b1 = *reinterpret_cast<const float4*>(&Bs[cur][k][64 + tx * 4]);
            float a[8] = {a0.x, a0.y, a0.z, a0.w, a1.x, a1.y, a1.z, a1.w};
            float b[8] = {b0.x, b0.y, b0.z, b0.w, b1.x, b1.y, b1.z, b1.w};
            #pragma unroll
            for (int i = 0; i < 8; i++)
                #pragma unroll
                for (int j = 0; j < 8; j++)
                    acc[i][j] += a[i] * b[j];
        }
        if (kb < 7) {
            int nxt = cur ^ 1;
            As[nxt][akq + 0][arow] = an.x;
            As[nxt][akq + 1][arow] = an.y;
            As[nxt][akq + 2][arow] = an.z;
            As[nxt][akq + 3][arow] = an.w;
            Bs[nxt][akq + 0][arow] = bn.x;
            Bs[nxt][akq + 1][arow] = bn.y;
            Bs[nxt][akq + 2][arow] = bn.z;
            Bs[nxt][akq + 3][arow] = bn.w;
            __syncthreads();
        }
    }

    #pragma unroll
    for (int i = 0; i < 8; i++) {
        int r = (i < 4) ? (ty * 4 + i) : (64 + ty * 4 + (i - 4));
        unsigned* dst = gsu + (size_t)(bh * Tc + q0 + r) * Tc + k0;
        uint4 u0, u1;
        u0.x = f2u(acc[i][0] * 0.125f); u0.y = f2u(acc[i][1] * 0.125f);
        u0.z = f2u(acc[i][2] * 0.125f); u0.w = f2u(acc[i][3] * 0.125f);
        u1.x = f2u(acc[i][4] * 0.125f); u1.y = f2u(acc[i][5] * 0.125f);
        u1.z = f2u(acc[i][6] * 0.125f); u1.w = f2u(acc[i][7] * 0.125f);
        *reinterpret_cast<uint4*>(dst + tx * 4)      = u0;
        *reinterpret_cast<uint4*>(dst + 64 + tx * 4) = u1;
    }
}

// ---------------------------------------------------------------------------
// Select kernel: r13-exact structure (measured best) with ONE change:
// pass-1 histogram sweep uses uint4 loads (same atomics, 1/4 iterations).
// ---------------------------------------------------------------------------
struct SelSmem {
    int hist[8][256];            // 8 KB
    unsigned short sidx[8][512]; // 8 KB
    float prob[8][512];          // 16 KB
};

__global__ void __launch_bounds__(256, 6)
select_kernel(const unsigned* __restrict__ gsu, const float* __restrict__ V,
              float* __restrict__ Y)
{
    __shared__ SelSmem S;

    int warp = threadIdx.x >> 5;
    int lane = threadIdx.x & 31;

    int bh = blockIdx.y;
    int qi = ((int)gridDim.x - 1 - (int)blockIdx.x) * 8 + warp;  // long rows first
    int n = qi + 1;

    const unsigned* su = gsu + (size_t)(bh * Tc + qi) * Tc;
    const float* Vb = V + (size_t)bh * Tc * HDc;
    int* hist = S.hist[warp];

    // ---- exact rank-64 threshold: 4-pass byte radix
    unsigned thrU = 0u;
    if (n > TOPKc) {
        unsigned pref = 0u; int need = TOPKc;
        #pragma unroll 1
        for (int by = 3; by >= 0; --by) {
            int sh = by * 8;
            #pragma unroll
            for (int b = lane; b < 256; b += 32) hist[b] = 0;
            __syncwarp();
            if (by == 3) {
                // vectorized: uint4 groups then scalar remainder
                int nvec = n >> 7;
                const uint4* su4 = reinterpret_cast<const uint4*>(su);
                for (int g = 0; g < nvec; g++) {
                    uint4 u = su4[g * 32 + lane];
                    atomicAdd(&hist[u.x >> 24], 1);
                    atomicAdd(&hist[u.y >> 24], 1);
                    atomicAdd(&hist[u.z >> 24], 1);
                    atomicAdd(&hist[u.w >> 24], 1);
                }
                for (int k = nvec * 128 + lane; k < n; k += 32)
                    atomicAdd(&hist[su[k] >> 24], 1);
            } else {
                unsigned hp = pref >> (sh + 8);
                for (int k = lane; k < n; k += 32) {
                    unsigned u = su[k];
                    if ((u >> (sh + 8)) == hp)
                        atomicAdd(&hist[(u >> sh) & 255u], 1);
                }
            }
            __syncwarp();
            int s = 0;
            #pragma unroll
            for (int j = 0; j < 8; j++) s += hist[255 - lane * 8 - j];
            int cum = s;
            #pragma unroll
            for (int off = 1; off < 32; off <<= 1) {
                int v = __shfl_up_sync(0xffffffffu, cum, off);
                if (lane >= off) cum += v;
            }
            unsigned bal = __ballot_sync(0xffffffffu, cum >= need);
            int selL = __ffs(bal) - 1;
            int above = __shfl_sync(0xffffffffu, cum - s, selL);
            int sneed = need - above;
            int res = 0;
            if (lane == selL) {
                int c = 0;
                #pragma unroll 1
                for (int j = 0; j < 8; j++) {
                    int b = 255 - selL * 8 - j;
                    int h = hist[b];
                    if (c + h >= sneed) { res = (b << 16) | (sneed - c); break; }
                    c += h;
                }
            }
            res = __shfl_sync(0xffffffffu, res, selL);
            pref |= (unsigned)(res >> 16) << sh;
            need = res & 0xffff;
        }
        thrU = pref;
    }
    __syncwarp();

    // ---- ballot compaction (ordered) + row max
    unsigned short* sidx = S.sidx[warp];
    int m = 0; unsigned umax = 0u;
    #pragma unroll 1
    for (int k0 = 0; k0 < n; k0 += 32) {
        int k = k0 + lane;
        bool a = k < n;
        unsigned u = a ? su[k] : 0u;
        umax = max(umax, u);
        bool keep = a && (u >= thrU);
        unsigned bal = __ballot_sync(0xffffffffu, keep);
        if (keep) {
            int pos = m + __popc(bal & ((1u << lane) - 1u));
            if (pos < 512) sidx[pos] = (unsigned short)k;
        }
        m += __popc(bal);
    }
    if (m > 512) m = 512;
    #pragma unroll
    for (int off = 16; off; off >>= 1)
        umax = max(umax, __shfl_xor_sync(0xffffffffu, umax, off));

    // ---- softmax over survivors -> dense prob buffer
    float maxf = u2f(umax);
    float lsum = 0.f;
    for (int j = lane; j < m; j += 32) {
        int k = sidx[j];
        float p = __expf(u2f(su[k]) - maxf);
        S.prob[warp][j] = p;
        lsum += p;
    }
    __syncwarp();
    #pragma unroll
    for (int off = 16; off; off >>= 1) lsum += __shfl_xor_sync(0xffffffffu, lsum, off);
    float rinv = 1.0f / lsum;

    // ---- sparse PV
    const float2* V2 = reinterpret_cast<const float2*>(Vb);
    const float* pr = S.prob[warp];
    float2 y = make_float2(0.f, 0.f);
    int j = 0;
    for (; j + 4 <= m; j += 4) {
        int k0 = sidx[j + 0], k1 = sidx[j + 1], k2 = sidx[j + 2], k3 = sidx[j + 3];
        float p0 = pr[j + 0], p1 = pr[j + 1], p2 = pr[j + 2], p3 = pr[j + 3];
        float2 v0 = V2[(size_t)k0 * 32 + lane];
        float2 v1 = V2[(size_t)k1 * 32 + lane];
        float2 v2 = V2[(size_t)k2 * 32 + lane];
        float2 v3 = V2[(size_t)k3 * 32 + lane];
        y.x += p0 * v0.x + p1 * v1.x + p2 * v2.x + p3 * v3.x;
        y.y += p0 * v0.y + p1 * v1.y + p2 * v2.y + p3 * v3.y;
    }
    for (; j < m; j++) {
        int k = sidx[j];
        float p = pr[j];
        float2 v = V2[(size_t)k * 32 + lane];
        y.x += p * v.x; y.y += p * v.y;
    }
    int b = bh >> 3, h = bh & 7;
    *reinterpret_cast<float2*>(Y + (size_t)(b * Tc + qi) * Cc + h * HDc + lane * 2) =
        make_float2(y.x * rinv, y.y * rinv);
}

// ---------------------------------------------------------------------------
extern "C" void kernel_launch(void* const* d_in, const int* in_sizes, int n_in,
                              void* d_out, int out_size)
{
    const float* q  = (const float*)d_in[0];
    const float* Wq = (const float*)d_in[2];
    const float* bq = (const float*)d_in[3];
    const float* Wk = (const float*)d_in[4];
    const float* bk = (const float*)d_in[5];
    const float* Wv = (const float*)d_in[6];
    const float* bv = (const float*)d_in[7];
    const float* Wp = (const float*)d_in[8];
    const float* bp = (const float*)d_in[9];

    float *Qh, *Kh, *Vh, *Yb;
    unsigned* SU;
    cudaGetSymbolAddress((void**)&Qh, g_Qh);
    cudaGetSymbolAddress((void**)&Kh, g_Kh);
    cudaGetSymbolAddress((void**)&Vh, g_Vh);
    cudaGetSymbolAddress((void**)&Yb, g_Y);
    cudaGetSymbolAddress((void**)&SU, g_SU);

    qkv_kernel<<<dim3(Cc / 128, Mr / 128, 3), 256>>>(q, Wq, bq, Wk, bk, Wv, bv, Qh, Kh, Vh);
    score_kernel<<<dim3(Tc / 128, Tc / 128, BHc), 256>>>(Qh, Kh, SU);
    select_kernel<<<dim3(Tc / 8, BHc), 256>>>(SU, Vh, Yb);
    sgemm_kernel<<<dim3(Cc / 128, Mr / 64), 256>>>(Yb, Wp, bp, (float*)d_out);
}

// round 17
// speedup vs baseline: 1.1154x; 1.0214x over previous
#include <cuda_runtime.h>

#define Bc 2
#define Tc 2048
#define Cc 512
#define Hc 8
#define HDc 64
#define TOPKc 64
#define BHc (Bc*Hc)
#define Mr (Bc*Tc)

// Scratch (device globals; allocations forbidden)
__device__ float g_Qh[BHc*Tc*HDc];
__device__ float g_Kh[BHc*Tc*HDc];
__device__ float g_Vh[BHc*Tc*HDc];
__device__ float g_Y [Bc*Tc*Cc];
__device__ unsigned g_SU[(size_t)BHc*Tc*Tc];   // scores as ordered uints

// ---------------------------------------------------------------------------
// helpers
// ---------------------------------------------------------------------------
__device__ __forceinline__ unsigned f2u(float f) {
    unsigned b = __float_as_uint(f);
    return b ^ ((unsigned)((int)b >> 31) | 0x80000000u);
}
__device__ __forceinline__ float u2f(unsigned u) {
    unsigned b = (u & 0x80000000u) ? (u ^ 0x80000000u) : ~u;
    return __uint_as_float(b);
}

// pick bin containing rank `need` scanning 255..0; returns (byte<<16)|rem_need
__device__ __forceinline__ int radix_pick(const int* hist, int need, int lane) {
    int s = 0;
    #pragma unroll
    for (int j = 0; j < 8; j++) s += hist[255 - lane * 8 - j];
    int cum = s;
    #pragma unroll
    for (int off = 1; off < 32; off <<= 1) {
        int v = __shfl_up_sync(0xffffffffu, cum, off);
        if (lane >= off) cum += v;
    }
    unsigned bal = __ballot_sync(0xffffffffu, cum >= need);
    int selL = __ffs(bal) - 1;
    int above = __shfl_sync(0xffffffffu, cum - s, selL);
    int sneed = need - above;
    int res = 0;
    if (lane == selL) {
        int c = 0;
        #pragma unroll 1
        for (int j = 0; j < 8; j++) {
            int b = 255 - selL * 8 - j;
            int h = hist[b];
            if (c + h >= sneed) { res = (b << 16) | (sneed - c); break; }
            c += h;
        }
    }
    return __shfl_sync(0xffffffffu, res, selL);
}

// ---------------------------------------------------------------------------
// Fused QKV GEMM (round-8 exact, measured 157us).
// ---------------------------------------------------------------------------
__global__ void __launch_bounds__(256, 2)
qkv_kernel(const float* __restrict__ A,
           const float* __restrict__ Wq, const float* __restrict__ bq,
           const float* __restrict__ Wk, const float* __restrict__ bk,
           const float* __restrict__ Wv, const float* __restrict__ bv,
           float* __restrict__ Qh, float* __restrict__ Kh, float* __restrict__ Vh)
{
    int z = blockIdx.z;
    const float* W    = (z == 0) ? Wq : (z == 1) ? Wk : Wv;
    const float* bias = (z == 0) ? bq : (z == 1) ? bk : bv;
    float* out        = (z == 0) ? Qh : (z == 1) ? Kh : Vh;

    __shared__ float As[2][8][128];
    __shared__ float Bs[2][8][128];

    int tid = threadIdx.x;
    int bm = blockIdx.y * 128;
    int bn = blockIdx.x * 128;
    int ty = tid >> 4;
    int tx = tid & 15;

    int arow = tid >> 1;
    int akq  = (tid & 1) * 4;
    int brow = tid >> 5;
    int bcol = (tid & 31) * 4;

    const float* Ag = A + (size_t)(bm + arow) * Cc + akq;
    const float* Wg = W + (size_t)brow * Cc + bn + bcol;

    float acc[8][8];
    #pragma unroll
    for (int i = 0; i < 8; i++)
        #pragma unroll
        for (int j = 0; j < 8; j++) acc[i][j] = 0.f;

    {
        float4 av = *reinterpret_cast<const float4*>(Ag);
        float4 bv4 = *reinterpret_cast<const float4*>(Wg);
        As[0][akq + 0][arow] = av.x;
        As[0][akq + 1][arow] = av.y;
        As[0][akq + 2][arow] = av.z;
        As[0][akq + 3][arow] = av.w;
        *reinterpret_cast<float4*>(&Bs[0][brow][bcol]) = bv4;
    }
    __syncthreads();

    #pragma unroll 1
    for (int kb = 0; kb < 64; kb++) {
        int cur = kb & 1;
        float4 an, bnv;
        if (kb < 63) {
            an  = *reinterpret_cast<const float4*>(Ag + (kb + 1) * 8);
            bnv = *reinterpret_cast<const float4*>(Wg + (size_t)(kb + 1) * 8 * Cc);
        }
        #pragma unroll
        for (int k = 0; k < 8; k++) {
            float4 a0 = *reinterpret_cast<const float4*>(&As[cur][k][ty * 4]);
            float4 a1 = *reinterpret_cast<const float4*>(&As[cur][k][64 + ty * 4]);
            float4 b0 = *reinterpret_cast<const float4*>(&Bs[cur][k][tx * 4]);
            float4 b1 = *reinterpret_cast<const float4*>(&Bs[cur][k][64 + tx * 4]);
            float a[8] = {a0.x, a0.y, a0.z, a0.w, a1.x, a1.y, a1.z, a1.w};
            float b[8] = {b0.x, b0.y, b0.z, b0.w, b1.x, b1.y, b1.z, b1.w};
            #pragma unroll
            for (int i = 0; i < 8; i++)
                #pragma unroll
                for (int j = 0; j < 8; j++)
                    acc[i][j] += a[i] * b[j];
        }
        if (kb < 63) {
            int nxt = cur ^ 1;
            As[nxt][akq + 0][arow] = an.x;
            As[nxt][akq + 1][arow] = an.y;
            As[nxt][akq + 2][arow] = an.z;
            As[nxt][akq + 3][arow] = an.w;
            *reinterpret_cast<float4*>(&Bs[nxt][brow][bcol]) = bnv;
            __syncthreads();
        }
    }

    float4 bia0 = *reinterpret_cast<const float4*>(bias + bn + tx * 4);
    float4 bia1 = *reinterpret_cast<const float4*>(bias + bn + 64 + tx * 4);
    #pragma unroll
    for (int i = 0; i < 8; i++) {
        int r = (i < 4) ? (ty * 4 + i) : (64 + ty * 4 + (i - 4));
        int mrow = bm + r;
        int b = mrow >> 11;
        int t = mrow & (Tc - 1);
        float4 o0 = make_float4(acc[i][0] + bia0.x, acc[i][1] + bia0.y,
                                acc[i][2] + bia0.z, acc[i][3] + bia0.w);
        float4 o1 = make_float4(acc[i][4] + bia1.x, acc[i][5] + bia1.y,
                                acc[i][6] + bia1.z, acc[i][7] + bia1.w);
        if (z == 2) {
            float ss0 = o0.x*o0.x + o0.y*o0.y + o0.z*o0.z + o0.w*o0.w;
            float ss1 = o1.x*o1.x + o1.y*o1.y + o1.z*o1.z + o1.w*o1.w;
            #pragma unroll
            for (int off = 8; off; off >>= 1) {
                ss0 += __shfl_xor_sync(0xffffffffu, ss0, off);
                ss1 += __shfl_xor_sync(0xffffffffu, ss1, off);
            }
            float sc0 = 1.0f / fmaxf(sqrtf(ss0), 1e-12f);
            float sc1 = 1.0f / fmaxf(sqrtf(ss1), 1e-12f);
            o0.x *= sc0; o0.y *= sc0; o0.z *= sc0; o0.w *= sc0;
            o1.x *= sc1; o1.y *= sc1; o1.z *= sc1; o1.w *= sc1;
        }
        int n0 = bn + tx * 4;       int h0 = n0 >> 6, d0 = n0 & 63;
        int n1 = bn + 64 + tx * 4;  int h1 = n1 >> 6, d1 = n1 & 63;
        *reinterpret_cast<float4*>(out + ((size_t)((b * Hc + h0) * Tc + t) << 6) + d0) = o0;
        *reinterpret_cast<float4*>(out + ((size_t)((b * Hc + h1) * Tc + t) << 6) + d1) = o1;
    }
}

// ---------------------------------------------------------------------------
// Output projection GEMM (r13 exact, measured 63us).
// ---------------------------------------------------------------------------
__global__ void __launch_bounds__(256, 2)
sgemm_kernel(const float* __restrict__ A, const float* __restrict__ W,
             const float* __restrict__ bias, float* __restrict__ out)
{
    __shared__ float As[2][8][128];
    __shared__ float Bs[2][8][128];

    int tid = threadIdx.x;
    int bm = blockIdx.y * 128;
    int bn = blockIdx.x * 128;
    int ty = tid >> 4;
    int tx = tid & 15;

    int arow = tid >> 1;
    int akq  = (tid & 1) * 4;
    int brow = tid >> 5;
    int bcol = (tid & 31) * 4;

    const float* Ag = A + (size_t)(bm + arow) * Cc + akq;
    const float* Wg = W + (size_t)brow * Cc + bn + bcol;

    float acc[8][8];
    #pragma unroll
    for (int i = 0; i < 8; i++)
        #pragma unroll
        for (int j = 0; j < 8; j++) acc[i][j] = 0.f;

    {
        float4 av = *reinterpret_cast<const float4*>(Ag);
        float4 bv4 = *reinterpret_cast<const float4*>(Wg);
        As[0][akq + 0][arow] = av.x;
        As[0][akq + 1][arow] = av.y;
        As[0][akq + 2][arow] = av.z;
        As[0][akq + 3][arow] = av.w;
        *reinterpret_cast<float4*>(&Bs[0][brow][bcol]) = bv4;
    }
    __syncthreads();

    #pragma unroll 1
    for (int kb = 0; kb < 64; kb++) {
        int cur = kb & 1;
        float4 an, bnv;
        if (kb < 63) {
            an  = *reinterpret_cast<const float4*>(Ag + (kb + 1) * 8);
            bnv = *reinterpret_cast<const float4*>(Wg + (size_t)(kb + 1) * 8 * Cc);
        }
        #pragma unroll
        for (int k = 0; k < 8; k++) {
            float4 a0 = *reinterpret_cast<const float4*>(&As[cur][k][ty * 4]);
            float4 a1 = *reinterpret_cast<const float4*>(&As[cur][k][64 + ty * 4]);
            float4 b0 = *reinterpret_cast<const float4*>(&Bs[cur][k][tx * 4]);
            float4 b1 = *reinterpret_cast<const float4*>(&Bs[cur][k][64 + tx * 4]);
            float a[8] = {a0.x, a0.y, a0.z, a0.w, a1.x, a1.y, a1.z, a1.w};
            float b[8] = {b0.x, b0.y, b0.z, b0.w, b1.x, b1.y, b1.z, b1.w};
            #pragma unroll
            for (int i = 0; i < 8; i++)
                #pragma unroll
                for (int j = 0; j < 8; j++)
                    acc[i][j] += a[i] * b[j];
        }
        if (kb < 63) {
            int nxt = cur ^ 1;
            As[nxt][akq + 0][arow] = an.x;
            As[nxt][akq + 1][arow] = an.y;
            As[nxt][akq + 2][arow] = an.z;
            As[nxt][akq + 3][arow] = an.w;
            *reinterpret_cast<float4*>(&Bs[nxt][brow][bcol]) = bnv;
            __syncthreads();
        }
    }

    float4 bia0 = *reinterpret_cast<const float4*>(bias + bn + tx * 4);
    float4 bia1 = *reinterpret_cast<const float4*>(bias + bn + 64 + tx * 4);
    #pragma unroll
    for (int i = 0; i < 8; i++) {
        int r = (i < 4) ? (ty * 4 + i) : (64 + ty * 4 + (i - 4));
        int mrow = bm + r;
        float4 o0 = make_float4(acc[i][0] + bia0.x, acc[i][1] + bia0.y,
                                acc[i][2] + bia0.z, acc[i][3] + bia0.w);
        float4 o1 = make_float4(acc[i][4] + bia1.x, acc[i][5] + bia1.y,
                                acc[i][6] + bia1.z, acc[i][7] + bia1.w);
        *reinterpret_cast<float4*>(out + (size_t)mrow * Cc + bn + tx * 4) = o0;
        *reinterpret_cast<float4*>(out + (size_t)mrow * Cc + bn + 64 + tx * 4) = o1;
    }
}

// ---------------------------------------------------------------------------
// Score GEMM (r13 exact): su[q][k] = f2u((Q.K)*0.125), 128x128 tile/block.
// ---------------------------------------------------------------------------
__global__ void __launch_bounds__(256, 2)
score_kernel(const float* __restrict__ Qh, const float* __restrict__ Kh,
             unsigned* __restrict__ gsu)
{
    if (blockIdx.x > blockIdx.y) return;
    int bh = blockIdx.z;
    int q0 = blockIdx.y * 128;
    int k0 = blockIdx.x * 128;

    __shared__ float As[2][8][128];
    __shared__ float Bs[2][8][128];

    int tid = threadIdx.x;
    int ty = tid >> 4;
    int tx = tid & 15;

    int arow = tid >> 1;
    int akq  = (tid & 1) * 4;

    const float* Ag = Qh + ((size_t)(bh * Tc + q0) + arow) * HDc + akq;
    const float* Bg = Kh + ((size_t)(bh * Tc + k0) + arow) * HDc + akq;

    float acc[8][8];
    #pragma unroll
    for (int i = 0; i < 8; i++)
        #pragma unroll
        for (int j = 0; j < 8; j++) acc[i][j] = 0.f;

    {
        float4 av = *reinterpret_cast<const float4*>(Ag);
        float4 bv = *reinterpret_cast<const float4*>(Bg);
        As[0][akq + 0][arow] = av.x;
        As[0][akq + 1][arow] = av.y;
        As[0][akq + 2][arow] = av.z;
        As[0][akq + 3][arow] = av.w;
        Bs[0][akq + 0][arow] = bv.x;
        Bs[0][akq + 1][arow] = bv.y;
        Bs[0][akq + 2][arow] = bv.z;
        Bs[0][akq + 3][arow] = bv.w;
    }
    __syncthreads();

    #pragma unroll 1
    for (int kb = 0; kb < 8; kb++) {
        int cur = kb & 1;
        float4 an, bn;
        if (kb < 7) {
            an = *reinterpret_cast<const float4*>(Ag + (kb + 1) * 8);
            bn = *reinterpret_cast<const float4*>(Bg + (kb + 1) * 8);
        }
        #pragma unroll
        for (int k = 0; k < 8; k++) {
            float4 a0 = *reinterpret_cast<const float4*>(&As[cur][k][ty * 4]);
            float4 a1 = *reinterpret_cast<const float4*>(&As[cur][k][64 + ty * 4]);
            float4 b0 = *reinterpret_cast<const float4*>(&Bs[cur][k][tx * 4]);
            float4 b1 = *reinterpret_cast<const float4*>(&Bs[cur][k][64 + tx * 4]);
            float a[8] = {a0.x, a0.y, a0.z, a0.w, a1.x, a1.y, a1.z, a1.w};
            float b[8] = {b0.x, b0.y, b0.z, b0.w, b1.x, b1.y, b1.z, b1.w};
            #pragma unroll
            for (int i = 0; i < 8; i++)
                #pragma unroll
                for (int j = 0; j < 8; j++)
                    acc[i][j] += a[i] * b[j];
        }
        if (kb < 7) {
            int nxt = cur ^ 1;
            As[nxt][akq + 0][arow] = an.x;
            As[nxt][akq + 1][arow] = an.y;
            As[nxt][akq + 2][arow] = an.z;
            As[nxt][akq + 3][arow] = an.w;
            Bs[nxt][akq + 0][arow] = bn.x;
            Bs[nxt][akq + 1][arow] = bn.y;
            Bs[nxt][akq + 2][arow] = bn.z;
            Bs[nxt][akq + 3][arow] = bn.w;
            __syncthreads();
        }
    }

    #pragma unroll
    for (int i = 0; i < 8; i++) {
        int r = (i < 4) ? (ty * 4 + i) : (64 + ty * 4 + (i - 4));
        unsigned* dst = gsu + (size_t)(bh * Tc + q0 + r) * Tc + k0;
        uint4 u0, u1;
        u0.x = f2u(acc[i][0] * 0.125f); u0.y = f2u(acc[i][1] * 0.125f);
        u0.z = f2u(acc[i][2] * 0.125f); u0.w = f2u(acc[i][3] * 0.125f);
        u1.x = f2u(acc[i][4] * 0.125f); u1.y = f2u(acc[i][5] * 0.125f);
        u1.z = f2u(acc[i][6] * 0.125f); u1.w = f2u(acc[i][7] * 0.125f);
        *reinterpret_cast<uint4*>(dst + tx * 4)      = u0;
        *reinterpret_cast<uint4*>(dst + 64 + tx * 4) = u1;
    }
}

// ---------------------------------------------------------------------------
// Select kernel: r13 structure. Passes 1-2 identical (scalar sweeps,
// colliding atomics = measured-best). Passes 3-4 replaced by: compact the
// values whose top-16 bits match the pass-2 prefix (expected ~4-30), then an
// exact warp mini-select: thr = min{x : #{v > x} <= need-1}. Fallback to the
// full r13 passes 3-4 when the band holds > 96 values. Compaction/softmax/PV
// byte-identical to r13.
// ---------------------------------------------------------------------------
struct SelSmem {
    int hist[8][256];            // 8 KB
    unsigned short sidx[8][512]; // 8 KB
    float prob[8][512];          // 16 KB (also scratch for band values)
};

__global__ void __launch_bounds__(256, 6)
select_kernel(const unsigned* __restrict__ gsu, const float* __restrict__ V,
              float* __restrict__ Y)
{
    __shared__ SelSmem S;

    int warp = threadIdx.x >> 5;
    int lane = threadIdx.x & 31;
    unsigned ltmask = (1u << lane) - 1u;

    int bh = blockIdx.y;
    int qi = ((int)gridDim.x - 1 - (int)blockIdx.x) * 8 + warp;  // long rows first
    int n = qi + 1;

    const unsigned* su = gsu + (size_t)(bh * Tc + qi) * Tc;
    const float* Vb = V + (size_t)bh * Tc * HDc;
    int* hist = S.hist[warp];

    // ---- exact rank-64 threshold
    unsigned thrU = 0u;
    if (n > TOPKc) {
        unsigned pref = 0u; int need = TOPKc;
        // passes 1-2 (top two bytes), r13-exact
        #pragma unroll 1
        for (int by = 3; by >= 2; --by) {
            int sh = by * 8;
            #pragma unroll
            for (int b = lane; b < 256; b += 32) hist[b] = 0;
            __syncwarp();
            if (by == 3) {
                for (int k = lane; k < n; k += 32)
                    atomicAdd(&hist[su[k] >> 24], 1);
            } else {
                unsigned hp = pref >> (sh + 8);
                for (int k = lane; k < n; k += 32) {
                    unsigned u = su[k];
                    if ((u >> (sh + 8)) == hp)
                        atomicAdd(&hist[(u >> sh) & 255u], 1);
                }
            }
            __syncwarp();
            int res = radix_pick(hist, need, lane);
            pref |= (unsigned)(res >> 16) << sh;
            need = res & 0xffff;
        }

        // compact band values (top-16 bits == pref>>16) into prob scratch
        unsigned* bv = reinterpret_cast<unsigned*>(S.prob[warp]);
        unsigned hp16 = pref >> 16;
        int c = 0;
        #pragma unroll 1
        for (int k0 = 0; k0 < n; k0 += 32) {
            int k = k0 + lane;
            bool a = k < n;
            unsigned u = a ? su[k] : 0u;
            bool inb = a && ((u >> 16) == hp16);
            unsigned bal = __ballot_sync(0xffffffffu, inb);
            if (inb) {
                int p = c + __popc(bal & ltmask);
                if (p < 512) bv[p] = u;
            }
            c += __popc(bal);
        }
        __syncwarp();

        if (c <= 96) {
            // warp mini-select: thr = min{x in band : #{v > x} <= need-1}
            unsigned tmin = 0xFFFFFFFFu;
            for (int j = lane; j < c; j += 32) {
                unsigned x = bv[j];
                int g = 0;
                for (int t = 0; t < c; t++) g += (bv[t] > x) ? 1 : 0;
                if (g <= need - 1) tmin = min(tmin, x);
            }
            #pragma unroll
            for (int off = 16; off; off >>= 1)
                tmin = min(tmin, __shfl_xor_sync(0xffffffffu, tmin, off));
            thrU = tmin;
        } else {
            // fallback: r13 passes 3-4 over the full row
            #pragma unroll 1
            for (int by = 1; by >= 0; --by) {
                int sh = by * 8;
                #pragma unroll
                for (int b = lane; b < 256; b += 32) hist[b] = 0;
                __syncwarp();
                unsigned hp = pref >> (sh + 8);
                for (int k = lane; k < n; k += 32) {
                    unsigned u = su[k];
                    if ((u >> (sh + 8)) == hp)
                        atomicAdd(&hist[(u >> sh) & 255u], 1);
                }
                __syncwarp();
                int res = radix_pick(hist, need, lane);
                pref |= (unsigned)(res >> 16) << sh;
                need = res & 0xffff;
            }
            thrU = pref;
        }
    }
    __syncwarp();

    // ---- ballot compaction (ordered) + row max (r13-exact)
    unsigned short* sidx = S.sidx[warp];
    int m = 0; unsigned umax = 0u;
    #pragma unroll 1
    for (int k0 = 0; k0 < n; k0 += 32) {
        int k = k0 + lane;
        bool a = k < n;
        unsigned u = a ? su[k] : 0u;
        umax = max(umax, u);
        bool keep = a && (u >= thrU);
        unsigned bal = __ballot_sync(0xffffffffu, keep);
        if (keep) {
            int pos = m + __popc(bal & ltmask);
            if (pos < 512) sidx[pos] = (unsigned short)k;
        }
        m += __popc(bal);
    }
    if (m > 512) m = 512;
    #pragma unroll
    for (int off = 16; off; off >>= 1)
        umax = max(umax, __shfl_xor_sync(0xffffffffu, umax, off));

    // ---- softmax over survivors -> dense prob buffer (r13-exact)
    float maxf = u2f(umax);
    float lsum = 0.f;
    for (int j = lane; j < m; j += 32) {
        int k = sidx[j];
        float p = __expf(u2f(su[k]) - maxf);
        S.prob[warp][j] = p;
        lsum += p;
    }
    __syncwarp();
    #pragma unroll
    for (int off = 16; off; off >>= 1) lsum += __shfl_xor_sync(0xffffffffu, lsum, off);
    float rinv = 1.0f / lsum;

    // ---- sparse PV (r13-exact)
    const float2* V2 = reinterpret_cast<const float2*>(Vb);
    const float* pr = S.prob[warp];
    float2 y = make_float2(0.f, 0.f);
    int j = 0;
    for (; j + 4 <= m; j += 4) {
        int k0 = sidx[j + 0], k1 = sidx[j + 1], k2 = sidx[j + 2], k3 = sidx[j + 3];
        float p0 = pr[j + 0], p1 = pr[j + 1], p2 = pr[j + 2], p3 = pr[j + 3];
        float2 v0 = V2[(size_t)k0 * 32 + lane];
        float2 v1 = V2[(size_t)k1 * 32 + lane];
        float2 v2 = V2[(size_t)k2 * 32 + lane];
        float2 v3 = V2[(size_t)k3 * 32 + lane];
        y.x += p0 * v0.x + p1 * v1.x + p2 * v2.x + p3 * v3.x;
        y.y += p0 * v0.y + p1 * v1.y + p2 * v2.y + p3 * v3.y;
    }
    for (; j < m; j++) {
        int k = sidx[j];
        float p = pr[j];
        float2 v = V2[(size_t)k * 32 + lane];
        y.x += p * v.x; y.y += p * v.y;
    }
    int b = bh >> 3, h = bh & 7;
    *reinterpret_cast<float2*>(Y + (size_t)(b * Tc + qi) * Cc + h * HDc + lane * 2) =
        make_float2(y.x * rinv, y.y * rinv);
}

// ---------------------------------------------------------------------------
extern "C" void kernel_launch(void* const* d_in, const int* in_sizes, int n_in,
                              void* d_out, int out_size)
{
    const float* q  = (const float*)d_in[0];
    const float* Wq = (const float*)d_in[2];
    const float* bq = (const float*)d_in[3];
    const float* Wk = (const float*)d_in[4];
    const float* bk = (const float*)d_in[5];
    const float* Wv = (const float*)d_in[6];
    const float* bv = (const float*)d_in[7];
    const float* Wp = (const float*)d_in[8];
    const float* bp = (const float*)d_in[9];

    float *Qh, *Kh, *Vh, *Yb;
    unsigned* SU;
    cudaGetSymbolAddress((void**)&Qh, g_Qh);
    cudaGetSymbolAddress((void**)&Kh, g_Kh);
    cudaGetSymbolAddress((void**)&Vh, g_Vh);
    cudaGetSymbolAddress((void**)&Yb, g_Y);
    cudaGetSymbolAddress((void**)&SU, g_SU);

    qkv_kernel<<<dim3(Cc / 128, Mr / 128, 3), 256>>>(q, Wq, bq, Wk, bk, Wv, bv, Qh, Kh, Vh);
    score_kernel<<<dim3(Tc / 128, Tc / 128, BHc), 256>>>(Qh, Kh, SU);
    select_kernel<<<dim3(Tc / 8, BHc), 256>>>(SU, Vh, Yb);
    sgemm_kernel<<<dim3(Cc / 128, Mr / 128), 256>>>(Yb, Wp, bp, (float*)d_out);
}